// round 5
// baseline (speedup 1.0000x reference)
#include <cuda_runtime.h>
#include <cuda_bf16.h>
#include <math.h>
#include <stdint.h>

#define BB 8
#define LL 512
#define DD 768
#define HH 12
#define DH 64
#define FF 3072
#define NL 6
#define NC 1
#define MM (BB*LL)   // 4096
#define NQKV 2304

typedef __nv_bfloat16 bf16;

// ---------------- scratch ----------------
__device__ float g_h[MM*DD];
__device__ bf16 g_xnh[MM*DD], g_xnl[MM*DD];
__device__ bf16 g_qkvh[MM*NQKV], g_qkvl[MM*NQKV];
__device__ bf16 g_aoh[MM*DD], g_aol[MM*DD];
__device__ bf16 g_ffh[MM*FF], g_ffl[MM*FF];
__device__ bf16 g_wqkvh[NL*NQKV*DD], g_wqkvl[NL*NQKV*DD];
__device__ bf16 g_woh[NL*DD*DD], g_wol[NL*DD*DD];
__device__ bf16 g_w1h[NL*DD*FF], g_w1l[NL*DD*FF];
__device__ bf16 g_w2h[NL*FF*DD], g_w2l[NL*FF*DD];
__device__ float g_bqkv[NL*NQKV];

// ---------------- PTX helpers ----------------
__device__ __forceinline__ uint32_t smem_to_u32(const void* p) {
    uint32_t a;
    asm("{ .reg .u64 t; cvta.to.shared.u64 t, %1; cvt.u32.u64 %0, t; }" : "=r"(a) : "l"(p));
    return a;
}
__device__ __forceinline__ void cp_async16(uint32_t saddr, const void* gaddr) {
    asm volatile("cp.async.cg.shared.global [%0], [%1], 16;" :: "r"(saddr), "l"(gaddr) : "memory");
}
#define CP_COMMIT() asm volatile("cp.async.commit_group;" ::: "memory")
#define CP_WAIT1()  asm volatile("cp.async.wait_group 1;"  ::: "memory")
__device__ __forceinline__ void ldsm4(uint32_t* r, uint32_t a) {
    asm volatile("ldmatrix.sync.aligned.m8n8.x4.shared.b16 {%0,%1,%2,%3}, [%4];"
        : "=r"(r[0]), "=r"(r[1]), "=r"(r[2]), "=r"(r[3]) : "r"(a));
}
__device__ __forceinline__ void ldsm4t(uint32_t* r, uint32_t a) {
    asm volatile("ldmatrix.sync.aligned.m8n8.x4.trans.shared.b16 {%0,%1,%2,%3}, [%4];"
        : "=r"(r[0]), "=r"(r[1]), "=r"(r[2]), "=r"(r[3]) : "r"(a));
}
__device__ __forceinline__ void mma_bf16(float* c, const uint32_t* a, const uint32_t* b) {
    asm volatile("mma.sync.aligned.m16n8k16.row.col.f32.bf16.bf16.f32 "
        "{%0,%1,%2,%3}, {%4,%5,%6,%7}, {%8,%9}, {%0,%1,%2,%3};"
        : "+f"(c[0]), "+f"(c[1]), "+f"(c[2]), "+f"(c[3])
        : "r"(a[0]), "r"(a[1]), "r"(a[2]), "r"(a[3]), "r"(b[0]), "r"(b[1]));
}
__device__ __forceinline__ uint32_t packbb(bf16 a, bf16 b) {
    __nv_bfloat162 t; t.x = a; t.y = b; return *(uint32_t*)&t;
}

// ---------------- weight transpose + bf16 split ----------------
__global__ void tsplit_kernel(const float* __restrict__ W, bf16* __restrict__ Th,
                              bf16* __restrict__ Tl, int K, int N,
                              int roff, size_t out_ls) {
    __shared__ float s[32][33];
    int l = blockIdx.z;
    const float* Wl = W + (size_t)l * K * N;
    bf16* Thl = Th + (size_t)l * out_ls;
    bf16* Tll = Tl + (size_t)l * out_ls;
    int n0 = blockIdx.x * 32, k0 = blockIdx.y * 32;
    int tx = threadIdx.x, ty = threadIdx.y;
    #pragma unroll
    for (int j = 0; j < 4; j++)
        s[ty + 8*j][tx] = Wl[(size_t)(k0 + ty + 8*j) * N + n0 + tx];
    __syncthreads();
    #pragma unroll
    for (int j = 0; j < 4; j++) {
        int row = ty + 8*j;
        float v = s[tx][row];
        bf16 hi = __float2bfloat16(v);
        bf16 lo = __float2bfloat16(v - __bfloat162float(hi));
        size_t idx = (size_t)(roff + n0 + row) * K + k0 + tx;
        Thl[idx] = hi; Tll[idx] = lo;
    }
}

__global__ void bias_concat(const float* __restrict__ bq, const float* __restrict__ bk,
                            const float* __restrict__ bv, float* __restrict__ o) {
    int l = blockIdx.y;
    int j = blockIdx.x * 256 + threadIdx.x;
    float v = (j < 768) ? bq[l*768 + j] : (j < 1536) ? bk[l*768 + j - 768] : bv[l*768 + j - 1536];
    o[l*NQKV + j] = v;
}

// ---------------- embedding + positional encoding ----------------
__global__ void embed_kernel(const int* __restrict__ x, const float* __restrict__ emb,
                             float* __restrict__ out) {
    int r = blockIdx.x;
    int b = r / LL;
    int tok = x[r];
    const float* erow = emb + (size_t)tok * DD;
    float* orow = out + (size_t)r * DD;
    const float neg_log = -logf(10000.0f) / (float)DD;
    for (int j = 0; j < 3; j++) {
        int d = threadIdx.x + j * 256;
        int i2 = (d >> 1) << 1;
        float div = expf((float)i2 * neg_log);
        float ang = (float)b * div;
        float pe = (d & 1) ? cosf(ang) : sinf(ang);
        orow[d] = erow[d] + pe;
    }
}

// ---------------- layernorm -> bf16 hi/lo ----------------
__global__ void ln_kernel(const float* __restrict__ in, const float* __restrict__ g,
                          const float* __restrict__ be,
                          bf16* __restrict__ oh, bf16* __restrict__ ol) {
    __shared__ float red[256];
    int r = blockIdx.x;
    int t = threadIdx.x;
    const float* xr = in + (size_t)r * DD;
    float v0 = xr[t], v1 = xr[t + 256], v2 = xr[t + 512];
    red[t] = v0 + v1 + v2;
    __syncthreads();
    for (int o = 128; o > 0; o >>= 1) { if (t < o) red[t] += red[t + o]; __syncthreads(); }
    float mean = red[0] * (1.0f / (float)DD);
    __syncthreads();
    float d0 = v0 - mean, d1 = v1 - mean, d2 = v2 - mean;
    red[t] = d0 * d0 + d1 * d1 + d2 * d2;
    __syncthreads();
    for (int o = 128; o > 0; o >>= 1) { if (t < o) red[t] += red[t + o]; __syncthreads(); }
    float var = red[0] * (1.0f / (float)DD);
    float rs = rsqrtf(var + 1e-5f);
    size_t base = (size_t)r * DD;
    float outs[3] = { d0 * rs * g[t] + be[t],
                      d1 * rs * g[t + 256] + be[t + 256],
                      d2 * rs * g[t + 512] + be[t + 512] };
    #pragma unroll
    for (int j = 0; j < 3; j++) {
        float v = outs[j];
        bf16 hi = __float2bfloat16(v);
        oh[base + t + 256*j] = hi;
        ol[base + t + 256*j] = __float2bfloat16(v - __bfloat162float(hi));
    }
}

// ---------------- HMMA GEMM: 128x128 CTA tile, warp tile 32x64 ----------------
// op: 0 = store fp32, 1 = GELU -> bf16 hi/lo, 2 = residual add fp32, 3 = store bf16 hi/lo
#define AH_OFF 0
#define AL_OFF 10240
#define BH_OFF 20480
#define BL_OFF 30720
#define STG_BYTES 40960
#define GEMM_SMEM (2*STG_BYTES)

__global__ __launch_bounds__(256) void gemm_mma(
    const bf16* __restrict__ Ah, const bf16* __restrict__ Al,
    const bf16* __restrict__ Bh, const bf16* __restrict__ Bl,
    const float* __restrict__ bias, float* __restrict__ C,
    bf16* __restrict__ Oh, bf16* __restrict__ Ol,
    int Ntot, int Ktot, int op)
{
    extern __shared__ char dsmem[];
    uint32_t smem_u = smem_to_u32(dsmem);
    int tid = threadIdx.x;
    int lane = tid & 31;
    int wid = tid >> 5;
    int wm = wid & 3;           // 4 m positions x 32
    int wn = wid >> 2;          // 2 n positions x 64
    int bm = blockIdx.y * 128, bn = blockIdx.x * 128;

    uint32_t a_off = (uint32_t)((wm*32 + (lane & 15)) * 80 + 16 * (lane >> 4));
    uint32_t b_off = (uint32_t)((wn*64 + 8*((lane >> 4) & 1) + (lane & 7)) * 80
                                + 16 * ((lane >> 3) & 1));

    // cp.async: 512 16B-chunks per operand (128 rows x 4), 2 per thread
    int r0 = tid >> 1,         c0 = (tid & 1) * 2;        // chunks 2*tid, 2*tid+1 -> row tid/2, cols {c0, c0+1}
    // simpler: chunk i = 2*tid + j, row = i>>2, col = i&3

    float acc[2][8][4];
    #pragma unroll
    for (int i = 0; i < 2; i++)
        #pragma unroll
        for (int j = 0; j < 8; j++)
            #pragma unroll
            for (int q = 0; q < 4; q++) acc[i][j][q] = 0.0f;

    int iters = Ktot >> 5;

    #define LOAD_STAGE(it, buf) do { \
        int k0 = (it) << 5; \
        uint32_t sb = smem_u + (buf) * STG_BYTES; \
        _Pragma("unroll") \
        for (int j = 0; j < 2; j++) { \
            int ci = 2*tid + j; \
            int row = ci >> 2, col = ci & 3; \
            uint32_t so = (uint32_t)(row*80 + col*16); \
            size_t ga = (size_t)(bm + row) * Ktot + k0 + col*8; \
            size_t gb = (size_t)(bn + row) * Ktot + k0 + col*8; \
            cp_async16(sb + AH_OFF + so, Ah + ga); \
            cp_async16(sb + AL_OFF + so, Al + ga); \
            cp_async16(sb + BH_OFF + so, Bh + gb); \
            cp_async16(sb + BL_OFF + so, Bl + gb); \
        } \
    } while (0)

    LOAD_STAGE(0, 0); CP_COMMIT();
    LOAD_STAGE(1, 1); CP_COMMIT();

    for (int it = 0; it < iters; it++) {
        CP_WAIT1();
        __syncthreads();
        int buf = it & 1;
        uint32_t sAh = smem_u + buf * STG_BYTES + AH_OFF;
        uint32_t sAl = smem_u + buf * STG_BYTES + AL_OFF;
        uint32_t sBh = smem_u + buf * STG_BYTES + BH_OFF;
        uint32_t sBl = smem_u + buf * STG_BYTES + BL_OFF;
        #pragma unroll
        for (int ks = 0; ks < 2; ks++) {
            uint32_t ah[2][4], al[2][4], bh[4][4], bl[4][4];
            #pragma unroll
            for (int tm = 0; tm < 2; tm++) {
                ldsm4(ah[tm], sAh + a_off + tm*1280 + ks*32);
                ldsm4(al[tm], sAl + a_off + tm*1280 + ks*32);
            }
            #pragma unroll
            for (int p = 0; p < 4; p++) {
                ldsm4(bh[p], sBh + b_off + p*1280 + ks*32);
                ldsm4(bl[p], sBl + b_off + p*1280 + ks*32);
            }
            // pass 1: Ah*Bh (16 independent accumulators)
            #pragma unroll
            for (int tm = 0; tm < 2; tm++)
                #pragma unroll
                for (int p = 0; p < 4; p++) {
                    mma_bf16(acc[tm][2*p],   ah[tm], &bh[p][0]);
                    mma_bf16(acc[tm][2*p+1], ah[tm], &bh[p][2]);
                }
            // pass 2: Ah*Bl
            #pragma unroll
            for (int tm = 0; tm < 2; tm++)
                #pragma unroll
                for (int p = 0; p < 4; p++) {
                    mma_bf16(acc[tm][2*p],   ah[tm], &bl[p][0]);
                    mma_bf16(acc[tm][2*p+1], ah[tm], &bl[p][2]);
                }
            // pass 3: Al*Bh
            #pragma unroll
            for (int tm = 0; tm < 2; tm++)
                #pragma unroll
                for (int p = 0; p < 4; p++) {
                    mma_bf16(acc[tm][2*p],   al[tm], &bh[p][0]);
                    mma_bf16(acc[tm][2*p+1], al[tm], &bh[p][2]);
                }
        }
        __syncthreads();
        if (it + 2 < iters) LOAD_STAGE(it + 2, buf);
        CP_COMMIT();
    }
    #undef LOAD_STAGE

    int m_base = bm + wm*32 + (lane >> 2);
    int n_base = bn + wn*64 + (lane & 3)*2;
    #pragma unroll
    for (int tm = 0; tm < 2; tm++) {
        #pragma unroll
        for (int tn = 0; tn < 8; tn++) {
            #pragma unroll
            for (int half = 0; half < 2; half++) {
                int m = m_base + tm*16 + half*8;
                int n = n_base + tn*8;
                float v0 = acc[tm][tn][2*half]     + bias[n];
                float v1 = acc[tm][tn][2*half + 1] + bias[n + 1];
                size_t idx = (size_t)m * Ntot + n;
                if (op == 1) {
                    float gv0 = 0.5f * v0 * (1.0f + erff(v0 * 0.70710678118654752f));
                    float gv1 = 0.5f * v1 * (1.0f + erff(v1 * 0.70710678118654752f));
                    bf16 h0 = __float2bfloat16(gv0), h1 = __float2bfloat16(gv1);
                    *(uint32_t*)(Oh + idx) = packbb(h0, h1);
                    *(uint32_t*)(Ol + idx) = packbb(
                        __float2bfloat16(gv0 - __bfloat162float(h0)),
                        __float2bfloat16(gv1 - __bfloat162float(h1)));
                } else if (op == 2) {
                    C[idx]     += v0;
                    C[idx + 1] += v1;
                } else if (op == 3) {
                    bf16 h0 = __float2bfloat16(v0), h1 = __float2bfloat16(v1);
                    *(uint32_t*)(Oh + idx) = packbb(h0, h1);
                    *(uint32_t*)(Ol + idx) = packbb(
                        __float2bfloat16(v0 - __bfloat162float(h0)),
                        __float2bfloat16(v1 - __bfloat162float(h1)));
                } else {
                    C[idx]     = v0;
                    C[idx + 1] = v1;
                }
            }
        }
    }
}

// ---------------- tensor-core fused attention ----------------
#define SSTR 520
#define OFF_Q  (64*SSTR*4)        // 133120
#define OFF_QL (OFF_Q + 9216)
#define OFF_K  (OFF_QL + 9216)    // 151552
#define OFF_KL (OFF_K + 18432)
#define ATTN_SMEM (OFF_KL + 18432) // 188416

__global__ __launch_bounds__(256) void attn_tc(
    const bf16* __restrict__ QKVh, const bf16* __restrict__ QKVl,
    const int* __restrict__ mask, float* __restrict__ attn_out,
    bf16* __restrict__ aoh, bf16* __restrict__ aol)
{
    extern __shared__ char sm[];
    float* S = (float*)sm;
    uint32_t su = smem_to_u32(sm);
    int tid = threadIdx.x, lane = tid & 31, wid = tid >> 5;
    int q0 = blockIdx.x * 64;
    int h = blockIdx.y, b = blockIdx.z;

    {
        int r = tid >> 2, c = tid & 3;
        size_t g = ((size_t)(b*LL + q0 + r)) * NQKV + h*DH;
        const uint4* gh = (const uint4*)(QKVh + g);
        const uint4* gl = (const uint4*)(QKVl + g);
        *(uint4*)(sm + OFF_Q  + r*144 + c*16)     = gh[c];
        *(uint4*)(sm + OFF_Q  + r*144 + (c+4)*16) = gh[c+4];
        *(uint4*)(sm + OFF_QL + r*144 + c*16)     = gl[c];
        *(uint4*)(sm + OFF_QL + r*144 + (c+4)*16) = gl[c+4];
    }

    int wm = wid & 1, wn = wid >> 1;

    for (int kc = 0; kc < 4; kc++) {
        {
            int r = tid >> 1, c0 = (tid & 1) * 4;
            size_t g = ((size_t)(b*LL + kc*128 + r)) * NQKV + 768 + h*DH;
            const uint4* gh = (const uint4*)(QKVh + g);
            const uint4* gl = (const uint4*)(QKVl + g);
            #pragma unroll
            for (int c = 0; c < 4; c++) {
                *(uint4*)(sm + OFF_K  + r*144 + (c0+c)*16) = gh[c0+c];
                *(uint4*)(sm + OFF_KL + r*144 + (c0+c)*16) = gl[c0+c];
            }
        }
        __syncthreads();
        float acc[2][4][4];
        #pragma unroll
        for (int i = 0; i < 2; i++)
            #pragma unroll
            for (int j = 0; j < 4; j++)
                #pragma unroll
                for (int q = 0; q < 4; q++) acc[i][j][q] = 0.0f;
        uint32_t aoff = (uint32_t)((wm*32 + (lane & 15)) * 144 + 16 * (lane >> 4));
        uint32_t boff = (uint32_t)((wn*32 + 8*((lane >> 4) & 1) + (lane & 7)) * 144
                                   + 16 * ((lane >> 3) & 1));
        #pragma unroll
        for (int ki = 0; ki < 4; ki++) {
            uint32_t ah[2][4], al[2][4], bh[2][4], bl[2][4];
            #pragma unroll
            for (int tm = 0; tm < 2; tm++) {
                ldsm4(ah[tm], su + OFF_Q  + aoff + tm*2304 + ki*32);
                ldsm4(al[tm], su + OFF_QL + aoff + tm*2304 + ki*32);
            }
            #pragma unroll
            for (int p = 0; p < 2; p++) {
                ldsm4(bh[p], su + OFF_K  + boff + p*2304 + ki*32);
                ldsm4(bl[p], su + OFF_KL + boff + p*2304 + ki*32);
            }
            #pragma unroll
            for (int tm = 0; tm < 2; tm++)
                #pragma unroll
                for (int p = 0; p < 2; p++) {
                    mma_bf16(acc[tm][2*p],   ah[tm], &bh[p][0]);
                    mma_bf16(acc[tm][2*p+1], ah[tm], &bh[p][2]);
                }
            #pragma unroll
            for (int tm = 0; tm < 2; tm++)
                #pragma unroll
                for (int p = 0; p < 2; p++) {
                    mma_bf16(acc[tm][2*p],   ah[tm], &bl[p][0]);
                    mma_bf16(acc[tm][2*p+1], ah[tm], &bl[p][2]);
                }
            #pragma unroll
            for (int tm = 0; tm < 2; tm++)
                #pragma unroll
                for (int p = 0; p < 2; p++) {
                    mma_bf16(acc[tm][2*p],   al[tm], &bh[p][0]);
                    mma_bf16(acc[tm][2*p+1], al[tm], &bh[p][2]);
                }
        }
        #pragma unroll
        for (int tm = 0; tm < 2; tm++) {
            #pragma unroll
            for (int tn = 0; tn < 4; tn++) {
                int row = wm*32 + tm*16 + (lane >> 2);
                int col = kc*128 + wn*32 + tn*8 + (lane & 3)*2;
                int m0 = mask[b*LL + col], m1 = mask[b*LL + col + 1];
                #pragma unroll
                for (int half = 0; half < 2; half++) {
                    int rr = row + half*8;
                    float v0 = acc[tm][tn][2*half]   * 0.125f - 0.01f * (float)((q0 + rr) - col);
                    float v1 = acc[tm][tn][2*half+1] * 0.125f - 0.01f * (float)((q0 + rr) - (col+1));
                    if (m0 == 0) v0 = -INFINITY;
                    if (m1 == 0) v1 = -INFINITY;
                    S[rr*SSTR + col]     = v0;
                    S[rr*SSTR + col + 1] = v1;
                }
            }
        }
        __syncthreads();
    }

    {
        size_t gbase0 = ((size_t)(b*HH + h) * LL + q0) * LL;
        #pragma unroll
        for (int j = 0; j < 8; j++) {
            int r = wid*8 + j;
            float4 e[4];
            #pragma unroll
            for (int i = 0; i < 4; i++) e[i] = *(float4*)&S[r*SSTR + i*128 + lane*4];
            float mx = -1e30f;
            #pragma unroll
            for (int i = 0; i < 4; i++)
                mx = fmaxf(mx, fmaxf(fmaxf(e[i].x, e[i].y), fmaxf(e[i].z, e[i].w)));
            #pragma unroll
            for (int o = 16; o > 0; o >>= 1) mx = fmaxf(mx, __shfl_xor_sync(0xFFFFFFFFu, mx, o));
            float sum = 0.0f;
            #pragma unroll
            for (int i = 0; i < 4; i++) {
                e[i].x = __expf(e[i].x - mx); e[i].y = __expf(e[i].y - mx);
                e[i].z = __expf(e[i].z - mx); e[i].w = __expf(e[i].w - mx);
                sum += e[i].x + e[i].y + e[i].z + e[i].w;
            }
            #pragma unroll
            for (int o = 16; o > 0; o >>= 1) sum += __shfl_xor_sync(0xFFFFFFFFu, sum, o);
            float inv = 1.0f / sum;
            float* gp = attn_out + gbase0 + (size_t)r * LL;
            #pragma unroll
            for (int i = 0; i < 4; i++) {
                e[i].x *= inv; e[i].y *= inv; e[i].z *= inv; e[i].w *= inv;
                *(float4*)&S[r*SSTR + i*128 + lane*4] = e[i];
                *(float4*)(gp + i*128 + lane*4) = e[i];
            }
        }
    }
    __syncthreads();

    float oa[2][2][4];
    #pragma unroll
    for (int i = 0; i < 2; i++)
        #pragma unroll
        for (int j = 0; j < 2; j++)
            #pragma unroll
            for (int q = 0; q < 4; q++) oa[i][j][q] = 0.0f;

    for (int kc = 0; kc < 8; kc++) {
        {
            int r = tid >> 2, c0 = (tid & 3) * 16;
            #pragma unroll
            for (int jj = 0; jj < 2; jj++) {
                const float* sp = &S[r*SSTR + kc*64 + c0 + jj*8];
                float v[8];
                *(float4*)&v[0] = *(const float4*)sp;
                *(float4*)&v[4] = *(const float4*)(sp + 4);
                uint32_t hw[4], lw[4];
                #pragma unroll
                for (int q = 0; q < 4; q++) {
                    bf16 ha = __float2bfloat16(v[2*q]), hb = __float2bfloat16(v[2*q+1]);
                    hw[q] = packbb(ha, hb);
                    lw[q] = packbb(__float2bfloat16(v[2*q]   - __bfloat162float(ha)),
                                   __float2bfloat16(v[2*q+1] - __bfloat162float(hb)));
                }
                *(uint4*)(sm + OFF_Q  + r*144 + (c0 + jj*8)*2) = *(uint4*)hw;
                *(uint4*)(sm + OFF_QL + r*144 + (c0 + jj*8)*2) = *(uint4*)lw;
            }
        }
        {
            int r = tid >> 2, c = tid & 3;
            size_t g = ((size_t)(b*LL + kc*64 + r)) * NQKV + 1536 + h*DH;
            const uint4* gh = (const uint4*)(QKVh + g);
            const uint4* gl = (const uint4*)(QKVl + g);
            *(uint4*)(sm + OFF_K  + r*144 + c*16)     = gh[c];
            *(uint4*)(sm + OFF_K  + r*144 + (c+4)*16) = gh[c+4];
            *(uint4*)(sm + OFF_KL + r*144 + c*16)     = gl[c];
            *(uint4*)(sm + OFF_KL + r*144 + (c+4)*16) = gl[c+4];
        }
        __syncthreads();
        uint32_t poff = (uint32_t)((wm*32 + (lane & 15)) * 144 + 16 * (lane >> 4));
        uint32_t voff = (uint32_t)((lane & 15) * 144 + wn*32 + 16 * (lane >> 4));
        #pragma unroll
        for (int ki = 0; ki < 4; ki++) {
            uint32_t ph[2][4], pl[2][4], vh[4], vl[4];
            #pragma unroll
            for (int tm = 0; tm < 2; tm++) {
                ldsm4(ph[tm], su + OFF_Q  + poff + tm*2304 + ki*32);
                ldsm4(pl[tm], su + OFF_QL + poff + tm*2304 + ki*32);
            }
            ldsm4t(vh, su + OFF_K  + voff + ki*2304);
            ldsm4t(vl, su + OFF_KL + voff + ki*2304);
            #pragma unroll
            for (int tm = 0; tm < 2; tm++)
                #pragma unroll
                for (int tn = 0; tn < 2; tn++)
                    mma_bf16(oa[tm][tn], ph[tm], &vh[2*tn]);
            #pragma unroll
            for (int tm = 0; tm < 2; tm++)
                #pragma unroll
                for (int tn = 0; tn < 2; tn++)
                    mma_bf16(oa[tm][tn], ph[tm], &vl[2*tn]);
            #pragma unroll
            for (int tm = 0; tm < 2; tm++)
                #pragma unroll
                for (int tn = 0; tn < 2; tn++)
                    mma_bf16(oa[tm][tn], pl[tm], &vh[2*tn]);
        }
        __syncthreads();
    }

    #pragma unroll
    for (int tm = 0; tm < 2; tm++) {
        #pragma unroll
        for (int tn = 0; tn < 2; tn++) {
            #pragma unroll
            for (int half = 0; half < 2; half++) {
                int row = wm*32 + tm*16 + (lane >> 2) + half*8;
                int col = wn*16 + tn*8 + (lane & 3)*2;
                float v0 = oa[tm][tn][2*half], v1 = oa[tm][tn][2*half+1];
                size_t g = ((size_t)(b*LL + q0 + row)) * DD + h*DH + col;
                bf16 h0 = __float2bfloat16(v0), h1 = __float2bfloat16(v1);
                *(uint32_t*)(aoh + g) = packbb(h0, h1);
                *(uint32_t*)(aol + g) = packbb(
                    __float2bfloat16(v0 - __bfloat162float(h0)),
                    __float2bfloat16(v1 - __bfloat162float(h1)));
            }
        }
    }
}

// ---------------- classifier head ----------------
__global__ void logits_kernel(const float* __restrict__ h, const float* __restrict__ Wc,
                              const float* __restrict__ bc, float* __restrict__ out) {
    __shared__ float red[256];
    int b = blockIdx.x;
    int t = threadIdx.x;
    float s = 0.0f;
    for (int d = t; d < DD; d += 256) s += h[(size_t)b * LL * DD + d] * Wc[d * NC];
    red[t] = s; __syncthreads();
    for (int o = 128; o > 0; o >>= 1) { if (t < o) red[t] += red[t + o]; __syncthreads(); }
    if (t == 0) out[b * NC] = red[0] + bc[0];
}

// ---------------- launcher ----------------
extern "C" void kernel_launch(void* const* d_in, const int* in_sizes, int n_in,
                              void* d_out, int out_size) {
    const int*   x    = (const int*)  d_in[0];
    const int*   mask = (const int*)  d_in[1];
    const float* emb  = (const float*)d_in[2];
    const float* Wq   = (const float*)d_in[3];
    const float* bq   = (const float*)d_in[4];
    const float* Wk   = (const float*)d_in[5];
    const float* bk   = (const float*)d_in[6];
    const float* Wv   = (const float*)d_in[7];
    const float* bv   = (const float*)d_in[8];
    const float* Wo   = (const float*)d_in[9];
    const float* bo   = (const float*)d_in[10];
    const float* W1   = (const float*)d_in[11];
    const float* b1   = (const float*)d_in[12];
    const float* W2   = (const float*)d_in[13];
    const float* b2   = (const float*)d_in[14];
    const float* g1   = (const float*)d_in[15];
    const float* be1  = (const float*)d_in[16];
    const float* g2   = (const float*)d_in[17];
    const float* be2  = (const float*)d_in[18];
    const float* Wc   = (const float*)d_in[19];
    const float* bc   = (const float*)d_in[20];

    float* out = (float*)d_out;
    float* logits = out;
    float* attn_base = out + (size_t)BB * NC;

    static bool attr_set = false;
    if (!attr_set) {
        cudaFuncSetAttribute(gemm_mma, cudaFuncAttributeMaxDynamicSharedMemorySize, GEMM_SMEM);
        cudaFuncSetAttribute(attn_tc, cudaFuncAttributeMaxDynamicSharedMemorySize, ATTN_SMEM);
        attr_set = true;
    }

    float *p_h, *p_bqkv;
    bf16 *p_xnh, *p_xnl, *p_qkvh, *p_qkvl, *p_aoh, *p_aol, *p_ffh, *p_ffl;
    bf16 *p_wqkvh, *p_wqkvl, *p_woh, *p_wol, *p_w1h, *p_w1l, *p_w2h, *p_w2l;
    cudaGetSymbolAddress((void**)&p_h, g_h);
    cudaGetSymbolAddress((void**)&p_bqkv, g_bqkv);
    cudaGetSymbolAddress((void**)&p_xnh, g_xnh); cudaGetSymbolAddress((void**)&p_xnl, g_xnl);
    cudaGetSymbolAddress((void**)&p_qkvh, g_qkvh); cudaGetSymbolAddress((void**)&p_qkvl, g_qkvl);
    cudaGetSymbolAddress((void**)&p_aoh, g_aoh); cudaGetSymbolAddress((void**)&p_aol, g_aol);
    cudaGetSymbolAddress((void**)&p_ffh, g_ffh); cudaGetSymbolAddress((void**)&p_ffl, g_ffl);
    cudaGetSymbolAddress((void**)&p_wqkvh, g_wqkvh); cudaGetSymbolAddress((void**)&p_wqkvl, g_wqkvl);
    cudaGetSymbolAddress((void**)&p_woh, g_woh); cudaGetSymbolAddress((void**)&p_wol, g_wol);
    cudaGetSymbolAddress((void**)&p_w1h, g_w1h); cudaGetSymbolAddress((void**)&p_w1l, g_w1l);
    cudaGetSymbolAddress((void**)&p_w2h, g_w2h); cudaGetSymbolAddress((void**)&p_w2l, g_w2l);

    dim3 tb(32, 8);
    size_t olsQKV = (size_t)NQKV * DD;
    tsplit_kernel<<<dim3(DD/32, DD/32, NL), tb>>>(Wq, p_wqkvh, p_wqkvl, DD, DD, 0,    olsQKV);
    tsplit_kernel<<<dim3(DD/32, DD/32, NL), tb>>>(Wk, p_wqkvh, p_wqkvl, DD, DD, 768,  olsQKV);
    tsplit_kernel<<<dim3(DD/32, DD/32, NL), tb>>>(Wv, p_wqkvh, p_wqkvl, DD, DD, 1536, olsQKV);
    tsplit_kernel<<<dim3(DD/32, DD/32, NL), tb>>>(Wo, p_woh, p_wol, DD, DD, 0, (size_t)DD*DD);
    tsplit_kernel<<<dim3(FF/32, DD/32, NL), tb>>>(W1, p_w1h, p_w1l, DD, FF, 0, (size_t)DD*FF);
    tsplit_kernel<<<dim3(DD/32, FF/32, NL), tb>>>(W2, p_w2h, p_w2l, FF, DD, 0, (size_t)FF*DD);
    bias_concat<<<dim3(NQKV/256, NL), 256>>>(bq, bk, bv, p_bqkv);

    embed_kernel<<<MM, 256>>>(x, emb, p_h);

    dim3 gD(DD/128, MM/128);
    dim3 gQKV(NQKV/128, MM/128);
    dim3 gF(FF/128, MM/128);
    dim3 gAttn(LL/64, HH, BB);

    for (int l = 0; l < NL; l++) {
        size_t wD = (size_t)l * DD * DD;
        size_t wF = (size_t)l * DD * FF;
        size_t wQ = (size_t)l * olsQKV;
        ln_kernel<<<MM, 256>>>(p_h, g1 + l*DD, be1 + l*DD, p_xnh, p_xnl);
        gemm_mma<<<gQKV, 256, GEMM_SMEM>>>(p_xnh, p_xnl, p_wqkvh + wQ, p_wqkvl + wQ,
                                           p_bqkv + l*NQKV, nullptr, p_qkvh, p_qkvl, NQKV, DD, 3);
        attn_tc<<<gAttn, 256, ATTN_SMEM>>>(p_qkvh, p_qkvl, mask,
                                           attn_base + (size_t)l * BB * HH * LL * LL, p_aoh, p_aol);
        gemm_mma<<<gD, 256, GEMM_SMEM>>>(p_aoh, p_aol, p_woh + wD, p_wol + wD, bo + l*DD,
                                         p_h, nullptr, nullptr, DD, DD, 2);
        ln_kernel<<<MM, 256>>>(p_h, g2 + l*DD, be2 + l*DD, p_xnh, p_xnl);
        gemm_mma<<<gF, 256, GEMM_SMEM>>>(p_xnh, p_xnl, p_w1h + wF, p_w1l + wF, b1 + l*FF,
                                         nullptr, p_ffh, p_ffl, FF, DD, 1);
        gemm_mma<<<gD, 256, GEMM_SMEM>>>(p_ffh, p_ffl, p_w2h + wF, p_w2l + wF, b2 + l*DD,
                                         p_h, nullptr, nullptr, DD, FF, 2);
    }

    logits_kernel<<<BB, 256>>>(p_h, Wc, bc, logits);
}

// round 6
// speedup vs baseline: 1.2302x; 1.2302x over previous
#include <cuda_runtime.h>
#include <cuda_bf16.h>
#include <math.h>
#include <stdint.h>

#define BB 8
#define LL 512
#define DD 768
#define HH 12
#define DH 64
#define FF 3072
#define NL 6
#define NC 1
#define MM (BB*LL)   // 4096
#define NQKV 2304

typedef __nv_bfloat16 bf16;

// ---------------- scratch ----------------
__device__ float g_h[MM*DD];
__device__ bf16 g_xnh[MM*DD], g_xnl[MM*DD];
__device__ bf16 g_qkvh[MM*NQKV], g_qkvl[MM*NQKV];
__device__ bf16 g_aoh[MM*DD], g_aol[MM*DD];
__device__ bf16 g_ffh[MM*FF], g_ffl[MM*FF];
__device__ bf16 g_wqkvh[NL*NQKV*DD], g_wqkvl[NL*NQKV*DD];
__device__ bf16 g_woh[NL*DD*DD], g_wol[NL*DD*DD];
__device__ bf16 g_w1h[NL*DD*FF], g_w1l[NL*DD*FF];
__device__ bf16 g_w2h[NL*FF*DD], g_w2l[NL*FF*DD];
__device__ float g_bqkv[NL*NQKV];

// ---------------- PTX helpers ----------------
__device__ __forceinline__ uint32_t smem_to_u32(const void* p) {
    uint32_t a;
    asm("{ .reg .u64 t; cvta.to.shared.u64 t, %1; cvt.u32.u64 %0, t; }" : "=r"(a) : "l"(p));
    return a;
}
__device__ __forceinline__ void cp_async16(uint32_t saddr, const void* gaddr) {
    asm volatile("cp.async.cg.shared.global [%0], [%1], 16;" :: "r"(saddr), "l"(gaddr) : "memory");
}
#define CP_COMMIT() asm volatile("cp.async.commit_group;" ::: "memory")
#define CP_WAIT2()  asm volatile("cp.async.wait_group 2;"  ::: "memory")
__device__ __forceinline__ void ldsm4(uint32_t* r, uint32_t a) {
    asm volatile("ldmatrix.sync.aligned.m8n8.x4.shared.b16 {%0,%1,%2,%3}, [%4];"
        : "=r"(r[0]), "=r"(r[1]), "=r"(r[2]), "=r"(r[3]) : "r"(a));
}
__device__ __forceinline__ void ldsm4t(uint32_t* r, uint32_t a) {
    asm volatile("ldmatrix.sync.aligned.m8n8.x4.trans.shared.b16 {%0,%1,%2,%3}, [%4];"
        : "=r"(r[0]), "=r"(r[1]), "=r"(r[2]), "=r"(r[3]) : "r"(a));
}
__device__ __forceinline__ void mma_bf16(float* c, const uint32_t* a, const uint32_t* b) {
    asm volatile("mma.sync.aligned.m16n8k16.row.col.f32.bf16.bf16.f32 "
        "{%0,%1,%2,%3}, {%4,%5,%6,%7}, {%8,%9}, {%0,%1,%2,%3};"
        : "+f"(c[0]), "+f"(c[1]), "+f"(c[2]), "+f"(c[3])
        : "r"(a[0]), "r"(a[1]), "r"(a[2]), "r"(a[3]), "r"(b[0]), "r"(b[1]));
}
__device__ __forceinline__ uint32_t packbb(bf16 a, bf16 b) {
    __nv_bfloat162 t; t.x = a; t.y = b; return *(uint32_t*)&t;
}

// ---------------- weight transpose + bf16 split ----------------
__global__ void tsplit_kernel(const float* __restrict__ W, bf16* __restrict__ Th,
                              bf16* __restrict__ Tl, int K, int N,
                              int roff, size_t out_ls) {
    __shared__ float s[32][33];
    int l = blockIdx.z;
    const float* Wl = W + (size_t)l * K * N;
    bf16* Thl = Th + (size_t)l * out_ls;
    bf16* Tll = Tl + (size_t)l * out_ls;
    int n0 = blockIdx.x * 32, k0 = blockIdx.y * 32;
    int tx = threadIdx.x, ty = threadIdx.y;
    #pragma unroll
    for (int j = 0; j < 4; j++)
        s[ty + 8*j][tx] = Wl[(size_t)(k0 + ty + 8*j) * N + n0 + tx];
    __syncthreads();
    #pragma unroll
    for (int j = 0; j < 4; j++) {
        int row = ty + 8*j;
        float v = s[tx][row];
        bf16 hi = __float2bfloat16(v);
        bf16 lo = __float2bfloat16(v - __bfloat162float(hi));
        size_t idx = (size_t)(roff + n0 + row) * K + k0 + tx;
        Thl[idx] = hi; Tll[idx] = lo;
    }
}

__global__ void bias_concat(const float* __restrict__ bq, const float* __restrict__ bk,
                            const float* __restrict__ bv, float* __restrict__ o) {
    int l = blockIdx.y;
    int j = blockIdx.x * 256 + threadIdx.x;
    float v = (j < 768) ? bq[l*768 + j] : (j < 1536) ? bk[l*768 + j - 768] : bv[l*768 + j - 1536];
    o[l*NQKV + j] = v;
}

// ---------------- embedding + positional encoding ----------------
__global__ void embed_kernel(const int* __restrict__ x, const float* __restrict__ emb,
                             float* __restrict__ out) {
    int r = blockIdx.x;
    int b = r / LL;
    int tok = x[r];
    const float* erow = emb + (size_t)tok * DD;
    float* orow = out + (size_t)r * DD;
    const float neg_log = -logf(10000.0f) / (float)DD;
    for (int j = 0; j < 3; j++) {
        int d = threadIdx.x + j * 256;
        int i2 = (d >> 1) << 1;
        float div = expf((float)i2 * neg_log);
        float ang = (float)b * div;
        float pe = (d & 1) ? cosf(ang) : sinf(ang);
        orow[d] = erow[d] + pe;
    }
}

// ---------------- layernorm -> bf16 hi/lo ----------------
__global__ void ln_kernel(const float* __restrict__ in, const float* __restrict__ g,
                          const float* __restrict__ be,
                          bf16* __restrict__ oh, bf16* __restrict__ ol) {
    __shared__ float red[256];
    int r = blockIdx.x;
    int t = threadIdx.x;
    const float* xr = in + (size_t)r * DD;
    float v0 = xr[t], v1 = xr[t + 256], v2 = xr[t + 512];
    red[t] = v0 + v1 + v2;
    __syncthreads();
    for (int o = 128; o > 0; o >>= 1) { if (t < o) red[t] += red[t + o]; __syncthreads(); }
    float mean = red[0] * (1.0f / (float)DD);
    __syncthreads();
    float d0 = v0 - mean, d1 = v1 - mean, d2 = v2 - mean;
    red[t] = d0 * d0 + d1 * d1 + d2 * d2;
    __syncthreads();
    for (int o = 128; o > 0; o >>= 1) { if (t < o) red[t] += red[t + o]; __syncthreads(); }
    float var = red[0] * (1.0f / (float)DD);
    float rs = rsqrtf(var + 1e-5f);
    size_t base = (size_t)r * DD;
    float outs[3] = { d0 * rs * g[t] + be[t],
                      d1 * rs * g[t + 256] + be[t + 256],
                      d2 * rs * g[t + 512] + be[t + 512] };
    #pragma unroll
    for (int j = 0; j < 3; j++) {
        float v = outs[j];
        bf16 hi = __float2bfloat16(v);
        oh[base + t + 256*j] = hi;
        ol[base + t + 256*j] = __float2bfloat16(v - __bfloat162float(hi));
    }
}

// ---------------- HMMA GEMM: 128x64 CTA tile, 3-stage cp.async pipeline ----------------
// op: 0 = store fp32, 1 = GELU -> bf16 hi/lo, 2 = residual add fp32, 3 = store bf16 hi/lo
#define STG_BYTES 30720
#define AL_OFF 10240
#define BH_OFF 20480
#define BL_OFF 25600
#define NSTG 3
#define GEMM_SMEM (NSTG*STG_BYTES)

__global__ __launch_bounds__(256) void gemm_mma(
    const bf16* __restrict__ Ah, const bf16* __restrict__ Al,
    const bf16* __restrict__ Bh, const bf16* __restrict__ Bl,
    const float* __restrict__ bias, float* __restrict__ C,
    bf16* __restrict__ Oh, bf16* __restrict__ Ol,
    int Ntot, int Ktot, int op)
{
    extern __shared__ char dsmem[];
    uint32_t smem_u = smem_to_u32(dsmem);
    int tid = threadIdx.x;
    int lane = tid & 31;
    int wid = tid >> 5;
    int wm = wid & 3;
    int wn = wid >> 2;
    int bm = blockIdx.y * 128, bn = blockIdx.x * 64;

    uint32_t a_off = (uint32_t)((wm*32 + (lane & 15)) * 80 + 16 * (lane >> 4));
    uint32_t b_off = (uint32_t)((wn*32 + 8*((lane >> 4) & 1) + (lane & 7)) * 80
                                + 16 * ((lane >> 3) & 1));

    int arow0 = tid >> 2,         ac0 = (tid & 3);
    int arow1 = (tid + 256) >> 2, ac1 = ((tid + 256) & 3);
    int brow  = tid >> 2,         bc  = (tid & 3);

    float acc[2][4][4];
    #pragma unroll
    for (int i = 0; i < 2; i++)
        #pragma unroll
        for (int j = 0; j < 4; j++)
            #pragma unroll
            for (int q = 0; q < 4; q++) acc[i][j][q] = 0.0f;

    int iters = Ktot >> 5;

    #define LOAD_STAGE(it, buf) do { \
        int k0 = (it) << 5; \
        uint32_t sb = smem_u + (buf) * STG_BYTES; \
        cp_async16(sb + arow0*80 + ac0*16,           Ah + (size_t)(bm + arow0) * Ktot + k0 + ac0*8); \
        cp_async16(sb + AL_OFF + arow0*80 + ac0*16,  Al + (size_t)(bm + arow0) * Ktot + k0 + ac0*8); \
        cp_async16(sb + arow1*80 + ac1*16,           Ah + (size_t)(bm + arow1) * Ktot + k0 + ac1*8); \
        cp_async16(sb + AL_OFF + arow1*80 + ac1*16,  Al + (size_t)(bm + arow1) * Ktot + k0 + ac1*8); \
        cp_async16(sb + BH_OFF + brow*80 + bc*16,    Bh + (size_t)(bn + brow) * Ktot + k0 + bc*8); \
        cp_async16(sb + BL_OFF + brow*80 + bc*16,    Bl + (size_t)(bn + brow) * Ktot + k0 + bc*8); \
    } while (0)

    LOAD_STAGE(0, 0); CP_COMMIT();
    LOAD_STAGE(1, 1); CP_COMMIT();
    LOAD_STAGE(2, 2); CP_COMMIT();

    int buf = 0;
    for (int it = 0; it < iters; it++) {
        CP_WAIT2();
        __syncthreads();
        uint32_t sA  = smem_u + buf * STG_BYTES;
        uint32_t sAl = sA + AL_OFF;
        uint32_t sBh = sA + BH_OFF;
        uint32_t sBl = sA + BL_OFF;
        #pragma unroll
        for (int ks = 0; ks < 2; ks++) {
            uint32_t ah[2][4], al[2][4], bh[2][4], bl[2][4];
            #pragma unroll
            for (int tm = 0; tm < 2; tm++) {
                ldsm4(ah[tm], sA  + a_off + tm*1280 + ks*32);
                ldsm4(al[tm], sAl + a_off + tm*1280 + ks*32);
            }
            #pragma unroll
            for (int p = 0; p < 2; p++) {
                ldsm4(bh[p], sBh + b_off + p*1280 + ks*32);
                ldsm4(bl[p], sBl + b_off + p*1280 + ks*32);
            }
            // pass 1: Ah*Bh
            #pragma unroll
            for (int tm = 0; tm < 2; tm++)
                #pragma unroll
                for (int p = 0; p < 2; p++) {
                    mma_bf16(acc[tm][2*p],   ah[tm], &bh[p][0]);
                    mma_bf16(acc[tm][2*p+1], ah[tm], &bh[p][2]);
                }
            // pass 2: Ah*Bl
            #pragma unroll
            for (int tm = 0; tm < 2; tm++)
                #pragma unroll
                for (int p = 0; p < 2; p++) {
                    mma_bf16(acc[tm][2*p],   ah[tm], &bl[p][0]);
                    mma_bf16(acc[tm][2*p+1], ah[tm], &bl[p][2]);
                }
            // pass 3: Al*Bh
            #pragma unroll
            for (int tm = 0; tm < 2; tm++)
                #pragma unroll
                for (int p = 0; p < 2; p++) {
                    mma_bf16(acc[tm][2*p],   al[tm], &bh[p][0]);
                    mma_bf16(acc[tm][2*p+1], al[tm], &bh[p][2]);
                }
        }
        __syncthreads();
        if (it + NSTG < iters) LOAD_STAGE(it + NSTG, buf);
        CP_COMMIT();
        buf = (buf == NSTG - 1) ? 0 : buf + 1;
    }
    #undef LOAD_STAGE

    int m_base = bm + wm*32 + (lane >> 2);
    int n_base = bn + wn*32 + (lane & 3)*2;
    #pragma unroll
    for (int tm = 0; tm < 2; tm++) {
        #pragma unroll
        for (int tn = 0; tn < 4; tn++) {
            #pragma unroll
            for (int half = 0; half < 2; half++) {
                int m = m_base + tm*16 + half*8;
                int n = n_base + tn*8;
                float v0 = acc[tm][tn][2*half]     + bias[n];
                float v1 = acc[tm][tn][2*half + 1] + bias[n + 1];
                size_t idx = (size_t)m * Ntot + n;
                if (op == 1) {
                    float gv0 = 0.5f * v0 * (1.0f + erff(v0 * 0.70710678118654752f));
                    float gv1 = 0.5f * v1 * (1.0f + erff(v1 * 0.70710678118654752f));
                    bf16 h0 = __float2bfloat16(gv0), h1 = __float2bfloat16(gv1);
                    *(uint32_t*)(Oh + idx) = packbb(h0, h1);
                    *(uint32_t*)(Ol + idx) = packbb(
                        __float2bfloat16(gv0 - __bfloat162float(h0)),
                        __float2bfloat16(gv1 - __bfloat162float(h1)));
                } else if (op == 2) {
                    C[idx]     += v0;
                    C[idx + 1] += v1;
                } else if (op == 3) {
                    bf16 h0 = __float2bfloat16(v0), h1 = __float2bfloat16(v1);
                    *(uint32_t*)(Oh + idx) = packbb(h0, h1);
                    *(uint32_t*)(Ol + idx) = packbb(
                        __float2bfloat16(v0 - __bfloat162float(h0)),
                        __float2bfloat16(v1 - __bfloat162float(h1)));
                } else {
                    C[idx]     = v0;
                    C[idx + 1] = v1;
                }
            }
        }
    }
}

// ---------------- tensor-core fused attention ----------------
#define SSTR 520
#define OFF_Q  (64*SSTR*4)
#define OFF_QL (OFF_Q + 9216)
#define OFF_K  (OFF_QL + 9216)
#define OFF_KL (OFF_K + 18432)
#define ATTN_SMEM (OFF_KL + 18432)

__global__ __launch_bounds__(256) void attn_tc(
    const bf16* __restrict__ QKVh, const bf16* __restrict__ QKVl,
    const int* __restrict__ mask, float* __restrict__ attn_out,
    bf16* __restrict__ aoh, bf16* __restrict__ aol)
{
    extern __shared__ char sm[];
    float* S = (float*)sm;
    uint32_t su = smem_to_u32(sm);
    int tid = threadIdx.x, lane = tid & 31, wid = tid >> 5;
    int q0 = blockIdx.x * 64;
    int h = blockIdx.y, b = blockIdx.z;

    {
        int r = tid >> 2, c = tid & 3;
        size_t g = ((size_t)(b*LL + q0 + r)) * NQKV + h*DH;
        const uint4* gh = (const uint4*)(QKVh + g);
        const uint4* gl = (const uint4*)(QKVl + g);
        *(uint4*)(sm + OFF_Q  + r*144 + c*16)     = gh[c];
        *(uint4*)(sm + OFF_Q  + r*144 + (c+4)*16) = gh[c+4];
        *(uint4*)(sm + OFF_QL + r*144 + c*16)     = gl[c];
        *(uint4*)(sm + OFF_QL + r*144 + (c+4)*16) = gl[c+4];
    }

    int wm = wid & 1, wn = wid >> 1;

    for (int kc = 0; kc < 4; kc++) {
        {
            int r = tid >> 1, c0 = (tid & 1) * 4;
            size_t g = ((size_t)(b*LL + kc*128 + r)) * NQKV + 768 + h*DH;
            const uint4* gh = (const uint4*)(QKVh + g);
            const uint4* gl = (const uint4*)(QKVl + g);
            #pragma unroll
            for (int c = 0; c < 4; c++) {
                *(uint4*)(sm + OFF_K  + r*144 + (c0+c)*16) = gh[c0+c];
                *(uint4*)(sm + OFF_KL + r*144 + (c0+c)*16) = gl[c0+c];
            }
        }
        __syncthreads();
        float acc[2][4][4];
        #pragma unroll
        for (int i = 0; i < 2; i++)
            #pragma unroll
            for (int j = 0; j < 4; j++)
                #pragma unroll
                for (int q = 0; q < 4; q++) acc[i][j][q] = 0.0f;
        uint32_t aoff = (uint32_t)((wm*32 + (lane & 15)) * 144 + 16 * (lane >> 4));
        uint32_t boff = (uint32_t)((wn*32 + 8*((lane >> 4) & 1) + (lane & 7)) * 144
                                   + 16 * ((lane >> 3) & 1));
        #pragma unroll
        for (int ki = 0; ki < 4; ki++) {
            uint32_t ah[2][4], al[2][4], bh[2][4], bl[2][4];
            #pragma unroll
            for (int tm = 0; tm < 2; tm++) {
                ldsm4(ah[tm], su + OFF_Q  + aoff + tm*2304 + ki*32);
                ldsm4(al[tm], su + OFF_QL + aoff + tm*2304 + ki*32);
            }
            #pragma unroll
            for (int p = 0; p < 2; p++) {
                ldsm4(bh[p], su + OFF_K  + boff + p*2304 + ki*32);
                ldsm4(bl[p], su + OFF_KL + boff + p*2304 + ki*32);
            }
            #pragma unroll
            for (int tm = 0; tm < 2; tm++)
                #pragma unroll
                for (int p = 0; p < 2; p++) {
                    mma_bf16(acc[tm][2*p],   ah[tm], &bh[p][0]);
                    mma_bf16(acc[tm][2*p+1], ah[tm], &bh[p][2]);
                }
            #pragma unroll
            for (int tm = 0; tm < 2; tm++)
                #pragma unroll
                for (int p = 0; p < 2; p++) {
                    mma_bf16(acc[tm][2*p],   ah[tm], &bl[p][0]);
                    mma_bf16(acc[tm][2*p+1], ah[tm], &bl[p][2]);
                }
            #pragma unroll
            for (int tm = 0; tm < 2; tm++)
                #pragma unroll
                for (int p = 0; p < 2; p++) {
                    mma_bf16(acc[tm][2*p],   al[tm], &bh[p][0]);
                    mma_bf16(acc[tm][2*p+1], al[tm], &bh[p][2]);
                }
        }
        #pragma unroll
        for (int tm = 0; tm < 2; tm++) {
            #pragma unroll
            for (int tn = 0; tn < 4; tn++) {
                int row = wm*32 + tm*16 + (lane >> 2);
                int col = kc*128 + wn*32 + tn*8 + (lane & 3)*2;
                int m0 = mask[b*LL + col], m1 = mask[b*LL + col + 1];
                #pragma unroll
                for (int half = 0; half < 2; half++) {
                    int rr = row + half*8;
                    float v0 = acc[tm][tn][2*half]   * 0.125f - 0.01f * (float)((q0 + rr) - col);
                    float v1 = acc[tm][tn][2*half+1] * 0.125f - 0.01f * (float)((q0 + rr) - (col+1));
                    if (m0 == 0) v0 = -INFINITY;
                    if (m1 == 0) v1 = -INFINITY;
                    S[rr*SSTR + col]     = v0;
                    S[rr*SSTR + col + 1] = v1;
                }
            }
        }
        __syncthreads();
    }

    {
        size_t gbase0 = ((size_t)(b*HH + h) * LL + q0) * LL;
        #pragma unroll
        for (int j = 0; j < 8; j++) {
            int r = wid*8 + j;
            float4 e[4];
            #pragma unroll
            for (int i = 0; i < 4; i++) e[i] = *(float4*)&S[r*SSTR + i*128 + lane*4];
            float mx = -1e30f;
            #pragma unroll
            for (int i = 0; i < 4; i++)
                mx = fmaxf(mx, fmaxf(fmaxf(e[i].x, e[i].y), fmaxf(e[i].z, e[i].w)));
            #pragma unroll
            for (int o = 16; o > 0; o >>= 1) mx = fmaxf(mx, __shfl_xor_sync(0xFFFFFFFFu, mx, o));
            float sum = 0.0f;
            #pragma unroll
            for (int i = 0; i < 4; i++) {
                e[i].x = __expf(e[i].x - mx); e[i].y = __expf(e[i].y - mx);
                e[i].z = __expf(e[i].z - mx); e[i].w = __expf(e[i].w - mx);
                sum += e[i].x + e[i].y + e[i].z + e[i].w;
            }
            #pragma unroll
            for (int o = 16; o > 0; o >>= 1) sum += __shfl_xor_sync(0xFFFFFFFFu, sum, o);
            float inv = 1.0f / sum;
            float* gp = attn_out + gbase0 + (size_t)r * LL;
            #pragma unroll
            for (int i = 0; i < 4; i++) {
                e[i].x *= inv; e[i].y *= inv; e[i].z *= inv; e[i].w *= inv;
                *(float4*)&S[r*SSTR + i*128 + lane*4] = e[i];
                *(float4*)(gp + i*128 + lane*4) = e[i];
            }
        }
    }
    __syncthreads();

    float oa[2][2][4];
    #pragma unroll
    for (int i = 0; i < 2; i++)
        #pragma unroll
        for (int j = 0; j < 2; j++)
            #pragma unroll
            for (int q = 0; q < 4; q++) oa[i][j][q] = 0.0f;

    for (int kc = 0; kc < 8; kc++) {
        {
            int r = tid >> 2, c0 = (tid & 3) * 16;
            #pragma unroll
            for (int jj = 0; jj < 2; jj++) {
                const float* sp = &S[r*SSTR + kc*64 + c0 + jj*8];
                float v[8];
                *(float4*)&v[0] = *(const float4*)sp;
                *(float4*)&v[4] = *(const float4*)(sp + 4);
                uint32_t hw[4], lw[4];
                #pragma unroll
                for (int q = 0; q < 4; q++) {
                    bf16 ha = __float2bfloat16(v[2*q]), hb = __float2bfloat16(v[2*q+1]);
                    hw[q] = packbb(ha, hb);
                    lw[q] = packbb(__float2bfloat16(v[2*q]   - __bfloat162float(ha)),
                                   __float2bfloat16(v[2*q+1] - __bfloat162float(hb)));
                }
                *(uint4*)(sm + OFF_Q  + r*144 + (c0 + jj*8)*2) = *(uint4*)hw;
                *(uint4*)(sm + OFF_QL + r*144 + (c0 + jj*8)*2) = *(uint4*)lw;
            }
        }
        {
            int r = tid >> 2, c = tid & 3;
            size_t g = ((size_t)(b*LL + kc*64 + r)) * NQKV + 1536 + h*DH;
            const uint4* gh = (const uint4*)(QKVh + g);
            const uint4* gl = (const uint4*)(QKVl + g);
            *(uint4*)(sm + OFF_K  + r*144 + c*16)     = gh[c];
            *(uint4*)(sm + OFF_K  + r*144 + (c+4)*16) = gh[c+4];
            *(uint4*)(sm + OFF_KL + r*144 + c*16)     = gl[c];
            *(uint4*)(sm + OFF_KL + r*144 + (c+4)*16) = gl[c+4];
        }
        __syncthreads();
        uint32_t poff = (uint32_t)((wm*32 + (lane & 15)) * 144 + 16 * (lane >> 4));
        uint32_t voff = (uint32_t)((lane & 15) * 144 + wn*32 + 16 * (lane >> 4));
        #pragma unroll
        for (int ki = 0; ki < 4; ki++) {
            uint32_t ph[2][4], pl[2][4], vh[4], vl[4];
            #pragma unroll
            for (int tm = 0; tm < 2; tm++) {
                ldsm4(ph[tm], su + OFF_Q  + poff + tm*2304 + ki*32);
                ldsm4(pl[tm], su + OFF_QL + poff + tm*2304 + ki*32);
            }
            ldsm4t(vh, su + OFF_K  + voff + ki*2304);
            ldsm4t(vl, su + OFF_KL + voff + ki*2304);
            #pragma unroll
            for (int tm = 0; tm < 2; tm++)
                #pragma unroll
                for (int tn = 0; tn < 2; tn++)
                    mma_bf16(oa[tm][tn], ph[tm], &vh[2*tn]);
            #pragma unroll
            for (int tm = 0; tm < 2; tm++)
                #pragma unroll
                for (int tn = 0; tn < 2; tn++)
                    mma_bf16(oa[tm][tn], ph[tm], &vl[2*tn]);
            #pragma unroll
            for (int tm = 0; tm < 2; tm++)
                #pragma unroll
                for (int tn = 0; tn < 2; tn++)
                    mma_bf16(oa[tm][tn], pl[tm], &vh[2*tn]);
        }
        __syncthreads();
    }

    #pragma unroll
    for (int tm = 0; tm < 2; tm++) {
        #pragma unroll
        for (int tn = 0; tn < 2; tn++) {
            #pragma unroll
            for (int half = 0; half < 2; half++) {
                int row = wm*32 + tm*16 + (lane >> 2) + half*8;
                int col = wn*16 + tn*8 + (lane & 3)*2;
                float v0 = oa[tm][tn][2*half], v1 = oa[tm][tn][2*half+1];
                size_t g = ((size_t)(b*LL + q0 + row)) * DD + h*DH + col;
                bf16 h0 = __float2bfloat16(v0), h1 = __float2bfloat16(v1);
                *(uint32_t*)(aoh + g) = packbb(h0, h1);
                *(uint32_t*)(aol + g) = packbb(
                    __float2bfloat16(v0 - __bfloat162float(h0)),
                    __float2bfloat16(v1 - __bfloat162float(h1)));
            }
        }
    }
}

// ---------------- classifier head ----------------
__global__ void logits_kernel(const float* __restrict__ h, const float* __restrict__ Wc,
                              const float* __restrict__ bc, float* __restrict__ out) {
    __shared__ float red[256];
    int b = blockIdx.x;
    int t = threadIdx.x;
    float s = 0.0f;
    for (int d = t; d < DD; d += 256) s += h[(size_t)b * LL * DD + d] * Wc[d * NC];
    red[t] = s; __syncthreads();
    for (int o = 128; o > 0; o >>= 1) { if (t < o) red[t] += red[t + o]; __syncthreads(); }
    if (t == 0) out[b * NC] = red[0] + bc[0];
}

// ---------------- launcher ----------------
extern "C" void kernel_launch(void* const* d_in, const int* in_sizes, int n_in,
                              void* d_out, int out_size) {
    const int*   x    = (const int*)  d_in[0];
    const int*   mask = (const int*)  d_in[1];
    const float* emb  = (const float*)d_in[2];
    const float* Wq   = (const float*)d_in[3];
    const float* bq   = (const float*)d_in[4];
    const float* Wk   = (const float*)d_in[5];
    const float* bk   = (const float*)d_in[6];
    const float* Wv   = (const float*)d_in[7];
    const float* bv   = (const float*)d_in[8];
    const float* Wo   = (const float*)d_in[9];
    const float* bo   = (const float*)d_in[10];
    const float* W1   = (const float*)d_in[11];
    const float* b1   = (const float*)d_in[12];
    const float* W2   = (const float*)d_in[13];
    const float* b2   = (const float*)d_in[14];
    const float* g1   = (const float*)d_in[15];
    const float* be1  = (const float*)d_in[16];
    const float* g2   = (const float*)d_in[17];
    const float* be2  = (const float*)d_in[18];
    const float* Wc   = (const float*)d_in[19];
    const float* bc   = (const float*)d_in[20];

    float* out = (float*)d_out;
    float* logits = out;
    float* attn_base = out + (size_t)BB * NC;

    static bool attr_set = false;
    if (!attr_set) {
        cudaFuncSetAttribute(gemm_mma, cudaFuncAttributeMaxDynamicSharedMemorySize, GEMM_SMEM);
        cudaFuncSetAttribute(attn_tc, cudaFuncAttributeMaxDynamicSharedMemorySize, ATTN_SMEM);
        attr_set = true;
    }

    float *p_h, *p_bqkv;
    bf16 *p_xnh, *p_xnl, *p_qkvh, *p_qkvl, *p_aoh, *p_aol, *p_ffh, *p_ffl;
    bf16 *p_wqkvh, *p_wqkvl, *p_woh, *p_wol, *p_w1h, *p_w1l, *p_w2h, *p_w2l;
    cudaGetSymbolAddress((void**)&p_h, g_h);
    cudaGetSymbolAddress((void**)&p_bqkv, g_bqkv);
    cudaGetSymbolAddress((void**)&p_xnh, g_xnh); cudaGetSymbolAddress((void**)&p_xnl, g_xnl);
    cudaGetSymbolAddress((void**)&p_qkvh, g_qkvh); cudaGetSymbolAddress((void**)&p_qkvl, g_qkvl);
    cudaGetSymbolAddress((void**)&p_aoh, g_aoh); cudaGetSymbolAddress((void**)&p_aol, g_aol);
    cudaGetSymbolAddress((void**)&p_ffh, g_ffh); cudaGetSymbolAddress((void**)&p_ffl, g_ffl);
    cudaGetSymbolAddress((void**)&p_wqkvh, g_wqkvh); cudaGetSymbolAddress((void**)&p_wqkvl, g_wqkvl);
    cudaGetSymbolAddress((void**)&p_woh, g_woh); cudaGetSymbolAddress((void**)&p_wol, g_wol);
    cudaGetSymbolAddress((void**)&p_w1h, g_w1h); cudaGetSymbolAddress((void**)&p_w1l, g_w1l);
    cudaGetSymbolAddress((void**)&p_w2h, g_w2h); cudaGetSymbolAddress((void**)&p_w2l, g_w2l);

    dim3 tb(32, 8);
    size_t olsQKV = (size_t)NQKV * DD;
    tsplit_kernel<<<dim3(DD/32, DD/32, NL), tb>>>(Wq, p_wqkvh, p_wqkvl, DD, DD, 0,    olsQKV);
    tsplit_kernel<<<dim3(DD/32, DD/32, NL), tb>>>(Wk, p_wqkvh, p_wqkvl, DD, DD, 768,  olsQKV);
    tsplit_kernel<<<dim3(DD/32, DD/32, NL), tb>>>(Wv, p_wqkvh, p_wqkvl, DD, DD, 1536, olsQKV);
    tsplit_kernel<<<dim3(DD/32, DD/32, NL), tb>>>(Wo, p_woh, p_wol, DD, DD, 0, (size_t)DD*DD);
    tsplit_kernel<<<dim3(FF/32, DD/32, NL), tb>>>(W1, p_w1h, p_w1l, DD, FF, 0, (size_t)DD*FF);
    tsplit_kernel<<<dim3(DD/32, FF/32, NL), tb>>>(W2, p_w2h, p_w2l, FF, DD, 0, (size_t)FF*DD);
    bias_concat<<<dim3(NQKV/256, NL), 256>>>(bq, bk, bv, p_bqkv);

    embed_kernel<<<MM, 256>>>(x, emb, p_h);

    dim3 gD(DD/64, MM/128);
    dim3 gQKV(NQKV/64, MM/128);
    dim3 gF(FF/64, MM/128);
    dim3 gAttn(LL/64, HH, BB);

    for (int l = 0; l < NL; l++) {
        size_t wD = (size_t)l * DD * DD;
        size_t wF = (size_t)l * DD * FF;
        size_t wQ = (size_t)l * olsQKV;
        ln_kernel<<<MM, 256>>>(p_h, g1 + l*DD, be1 + l*DD, p_xnh, p_xnl);
        gemm_mma<<<gQKV, 256, GEMM_SMEM>>>(p_xnh, p_xnl, p_wqkvh + wQ, p_wqkvl + wQ,
                                           p_bqkv + l*NQKV, nullptr, p_qkvh, p_qkvl, NQKV, DD, 3);
        attn_tc<<<gAttn, 256, ATTN_SMEM>>>(p_qkvh, p_qkvl, mask,
                                           attn_base + (size_t)l * BB * HH * LL * LL, p_aoh, p_aol);
        gemm_mma<<<gD, 256, GEMM_SMEM>>>(p_aoh, p_aol, p_woh + wD, p_wol + wD, bo + l*DD,
                                         p_h, nullptr, nullptr, DD, DD, 2);
        ln_kernel<<<MM, 256>>>(p_h, g2 + l*DD, be2 + l*DD, p_xnh, p_xnl);
        gemm_mma<<<gF, 256, GEMM_SMEM>>>(p_xnh, p_xnl, p_w1h + wF, p_w1l + wF, b1 + l*FF,
                                         nullptr, p_ffh, p_ffl, FF, DD, 1);
        gemm_mma<<<gD, 256, GEMM_SMEM>>>(p_ffh, p_ffl, p_w2h + wF, p_w2l + wF, b2 + l*DD,
                                         p_h, nullptr, nullptr, DD, FF, 2);
    }

    logits_kernel<<<BB, 256>>>(p_h, Wc, bc, logits);
}

// round 7
// speedup vs baseline: 1.3225x; 1.0751x over previous
#include <cuda_runtime.h>
#include <cuda_bf16.h>
#include <math.h>
#include <stdint.h>

#define BB 8
#define LL 512
#define DD 768
#define HH 12
#define DH 64
#define FF 3072
#define NL 6
#define NC 1
#define MM (BB*LL)   // 4096
#define NQKV 2304

typedef __nv_bfloat16 bf16;

// ---------------- scratch ----------------
__device__ float g_h[MM*DD];
__device__ bf16 g_xnh[MM*DD], g_xnl[MM*DD];
__device__ bf16 g_qkvh[MM*NQKV], g_qkvl[MM*NQKV];
__device__ bf16 g_aoh[MM*DD], g_aol[MM*DD];
__device__ bf16 g_ffh[MM*FF], g_ffl[MM*FF];
__device__ bf16 g_wqkvh[NL*NQKV*DD], g_wqkvl[NL*NQKV*DD];
__device__ bf16 g_woh[NL*DD*DD], g_wol[NL*DD*DD];
__device__ bf16 g_w1h[NL*DD*FF], g_w1l[NL*DD*FF];
__device__ bf16 g_w2h[NL*FF*DD], g_w2l[NL*FF*DD];
__device__ float g_bqkv[NL*NQKV];

// ---------------- PTX helpers ----------------
__device__ __forceinline__ uint32_t smem_to_u32(const void* p) {
    uint32_t a;
    asm("{ .reg .u64 t; cvta.to.shared.u64 t, %1; cvt.u32.u64 %0, t; }" : "=r"(a) : "l"(p));
    return a;
}
__device__ __forceinline__ void cp_async16(uint32_t saddr, const void* gaddr) {
    asm volatile("cp.async.cg.shared.global [%0], [%1], 16;" :: "r"(saddr), "l"(gaddr) : "memory");
}
#define CP_COMMIT() asm volatile("cp.async.commit_group;" ::: "memory")
#define CP_WAIT1()  asm volatile("cp.async.wait_group 1;"  ::: "memory")
__device__ __forceinline__ void ldsm4(uint32_t* r, uint32_t a) {
    asm volatile("ldmatrix.sync.aligned.m8n8.x4.shared.b16 {%0,%1,%2,%3}, [%4];"
        : "=r"(r[0]), "=r"(r[1]), "=r"(r[2]), "=r"(r[3]) : "r"(a));
}
__device__ __forceinline__ void ldsm4t(uint32_t* r, uint32_t a) {
    asm volatile("ldmatrix.sync.aligned.m8n8.x4.trans.shared.b16 {%0,%1,%2,%3}, [%4];"
        : "=r"(r[0]), "=r"(r[1]), "=r"(r[2]), "=r"(r[3]) : "r"(a));
}
__device__ __forceinline__ void mma_bf16(float* c, const uint32_t* a, const uint32_t* b) {
    asm volatile("mma.sync.aligned.m16n8k16.row.col.f32.bf16.bf16.f32 "
        "{%0,%1,%2,%3}, {%4,%5,%6,%7}, {%8,%9}, {%0,%1,%2,%3};"
        : "+f"(c[0]), "+f"(c[1]), "+f"(c[2]), "+f"(c[3])
        : "r"(a[0]), "r"(a[1]), "r"(a[2]), "r"(a[3]), "r"(b[0]), "r"(b[1]));
}
__device__ __forceinline__ uint32_t packbb(bf16 a, bf16 b) {
    __nv_bfloat162 t; t.x = a; t.y = b; return *(uint32_t*)&t;
}

// ---------------- weight transpose + bf16 split (generic) ----------------
__global__ void tsplit_kernel(const float* __restrict__ W, bf16* __restrict__ Th,
                              bf16* __restrict__ Tl, int K, int N,
                              int roff, size_t out_ls) {
    __shared__ float s[32][33];
    int l = blockIdx.z;
    const float* Wl = W + (size_t)l * K * N;
    bf16* Thl = Th + (size_t)l * out_ls;
    bf16* Tll = Tl + (size_t)l * out_ls;
    int n0 = blockIdx.x * 32, k0 = blockIdx.y * 32;
    int tx = threadIdx.x, ty = threadIdx.y;
    #pragma unroll
    for (int j = 0; j < 4; j++)
        s[ty + 8*j][tx] = Wl[(size_t)(k0 + ty + 8*j) * N + n0 + tx];
    __syncthreads();
    #pragma unroll
    for (int j = 0; j < 4; j++) {
        int row = ty + 8*j;
        float v = s[tx][row];
        bf16 hi = __float2bfloat16(v);
        bf16 lo = __float2bfloat16(v - __bfloat162float(hi));
        size_t idx = (size_t)(roff + n0 + row) * K + k0 + tx;
        Thl[idx] = hi; Tll[idx] = lo;
    }
}

// merged QKV tsplit: one launch handles Wq/Wk/Wv for all layers
__global__ void tsplit_qkv(const float* __restrict__ Wq, const float* __restrict__ Wk,
                           const float* __restrict__ Wv,
                           bf16* __restrict__ Th, bf16* __restrict__ Tl) {
    __shared__ float s[32][33];
    int z = blockIdx.z;
    int l = z / 3, which = z % 3;
    const float* W = (which == 0) ? Wq : (which == 1) ? Wk : Wv;
    const float* Wl = W + (size_t)l * DD * DD;
    size_t out_ls = (size_t)NQKV * DD;
    bf16* Thl = Th + (size_t)l * out_ls;
    bf16* Tll = Tl + (size_t)l * out_ls;
    int roff = which * DD;
    int n0 = blockIdx.x * 32, k0 = blockIdx.y * 32;
    int tx = threadIdx.x, ty = threadIdx.y;
    #pragma unroll
    for (int j = 0; j < 4; j++)
        s[ty + 8*j][tx] = Wl[(size_t)(k0 + ty + 8*j) * DD + n0 + tx];
    __syncthreads();
    #pragma unroll
    for (int j = 0; j < 4; j++) {
        int row = ty + 8*j;
        float v = s[tx][row];
        bf16 hi = __float2bfloat16(v);
        bf16 lo = __float2bfloat16(v - __bfloat162float(hi));
        size_t idx = (size_t)(roff + n0 + row) * DD + k0 + tx;
        Thl[idx] = hi; Tll[idx] = lo;
    }
}

__global__ void bias_concat(const float* __restrict__ bq, const float* __restrict__ bk,
                            const float* __restrict__ bv, float* __restrict__ o) {
    int l = blockIdx.y;
    int j = blockIdx.x * 256 + threadIdx.x;
    float v = (j < 768) ? bq[l*768 + j] : (j < 1536) ? bk[l*768 + j - 768] : bv[l*768 + j - 1536];
    o[l*NQKV + j] = v;
}

// ---------------- embedding + positional encoding ----------------
__global__ void embed_kernel(const int* __restrict__ x, const float* __restrict__ emb,
                             float* __restrict__ out) {
    int r = blockIdx.x;
    int b = r / LL;
    int tok = x[r];
    const float* erow = emb + (size_t)tok * DD;
    float* orow = out + (size_t)r * DD;
    const float neg_log = -logf(10000.0f) / (float)DD;
    for (int j = 0; j < 3; j++) {
        int d = threadIdx.x + j * 256;
        int i2 = (d >> 1) << 1;
        float div = expf((float)i2 * neg_log);
        float ang = (float)b * div;
        float pe = (d & 1) ? cosf(ang) : sinf(ang);
        orow[d] = erow[d] + pe;
    }
}

// ---------------- layernorm -> bf16 hi/lo ----------------
__global__ void ln_kernel(const float* __restrict__ in, const float* __restrict__ g,
                          const float* __restrict__ be,
                          bf16* __restrict__ oh, bf16* __restrict__ ol) {
    __shared__ float red[256];
    int r = blockIdx.x;
    int t = threadIdx.x;
    const float* xr = in + (size_t)r * DD;
    float v0 = xr[t], v1 = xr[t + 256], v2 = xr[t + 512];
    red[t] = v0 + v1 + v2;
    __syncthreads();
    for (int o = 128; o > 0; o >>= 1) { if (t < o) red[t] += red[t + o]; __syncthreads(); }
    float mean = red[0] * (1.0f / (float)DD);
    __syncthreads();
    float d0 = v0 - mean, d1 = v1 - mean, d2 = v2 - mean;
    red[t] = d0 * d0 + d1 * d1 + d2 * d2;
    __syncthreads();
    for (int o = 128; o > 0; o >>= 1) { if (t < o) red[t] += red[t + o]; __syncthreads(); }
    float var = red[0] * (1.0f / (float)DD);
    float rs = rsqrtf(var + 1e-5f);
    size_t base = (size_t)r * DD;
    float outs[3] = { d0 * rs * g[t] + be[t],
                      d1 * rs * g[t + 256] + be[t + 256],
                      d2 * rs * g[t + 512] + be[t + 512] };
    #pragma unroll
    for (int j = 0; j < 3; j++) {
        float v = outs[j];
        bf16 hi = __float2bfloat16(v);
        oh[base + t + 256*j] = hi;
        ol[base + t + 256*j] = __float2bfloat16(v - __bfloat162float(hi));
    }
}

// ---------------- HMMA GEMM: 128x64 CTA tile, 3-stage single-sync pipeline ----------------
// op: 0 = store fp32, 1 = GELU -> bf16 hi/lo, 2 = residual add fp32, 3 = store bf16 hi/lo
#define STG_BYTES 30720
#define AL_OFF 10240
#define BH_OFF 20480
#define BL_OFF 25600
#define NSTG 3
#define GEMM_SMEM (NSTG*STG_BYTES)

__global__ __launch_bounds__(256) void gemm_mma(
    const bf16* __restrict__ Ah, const bf16* __restrict__ Al,
    const bf16* __restrict__ Bh, const bf16* __restrict__ Bl,
    const float* __restrict__ bias, float* __restrict__ C,
    bf16* __restrict__ Oh, bf16* __restrict__ Ol,
    int Ntot, int Ktot, int op)
{
    extern __shared__ char dsmem[];
    uint32_t smem_u = smem_to_u32(dsmem);
    int tid = threadIdx.x;
    int lane = tid & 31;
    int wid = tid >> 5;
    int wm = wid & 3;
    int wn = wid >> 2;
    int bm = blockIdx.y * 128, bn = blockIdx.x * 64;

    uint32_t a_off = (uint32_t)((wm*32 + (lane & 15)) * 80 + 16 * (lane >> 4));
    uint32_t b_off = (uint32_t)((wn*32 + 8*((lane >> 4) & 1) + (lane & 7)) * 80
                                + 16 * ((lane >> 3) & 1));

    int arow0 = tid >> 2,         ac0 = (tid & 3);
    int arow1 = (tid + 256) >> 2, ac1 = ((tid + 256) & 3);
    int brow  = tid >> 2,         bc  = (tid & 3);

    float acc[2][4][4];
    #pragma unroll
    for (int i = 0; i < 2; i++)
        #pragma unroll
        for (int j = 0; j < 4; j++)
            #pragma unroll
            for (int q = 0; q < 4; q++) acc[i][j][q] = 0.0f;

    int iters = Ktot >> 5;

    #define LOAD_STAGE(it, buf) do { \
        int k0 = (it) << 5; \
        uint32_t sb = smem_u + (buf) * STG_BYTES; \
        cp_async16(sb + arow0*80 + ac0*16,           Ah + (size_t)(bm + arow0) * Ktot + k0 + ac0*8); \
        cp_async16(sb + AL_OFF + arow0*80 + ac0*16,  Al + (size_t)(bm + arow0) * Ktot + k0 + ac0*8); \
        cp_async16(sb + arow1*80 + ac1*16,           Ah + (size_t)(bm + arow1) * Ktot + k0 + ac1*8); \
        cp_async16(sb + AL_OFF + arow1*80 + ac1*16,  Al + (size_t)(bm + arow1) * Ktot + k0 + ac1*8); \
        cp_async16(sb + BH_OFF + brow*80 + bc*16,    Bh + (size_t)(bn + brow) * Ktot + k0 + bc*8); \
        cp_async16(sb + BL_OFF + brow*80 + bc*16,    Bl + (size_t)(bn + brow) * Ktot + k0 + bc*8); \
    } while (0)

    // prologue: NSTG-1 stages in flight
    LOAD_STAGE(0, 0); CP_COMMIT();
    LOAD_STAGE(1, 1); CP_COMMIT();

    int buf = 0;
    for (int it = 0; it < iters; it++) {
        // stage `it` ready; all prior-iteration readers fenced. ONE sync per iter.
        CP_WAIT1();
        __syncthreads();
        uint32_t sA  = smem_u + buf * STG_BYTES;
        uint32_t sAl = sA + AL_OFF;
        uint32_t sBh = sA + BH_OFF;
        uint32_t sBl = sA + BL_OFF;
        #pragma unroll
        for (int ks = 0; ks < 2; ks++) {
            uint32_t ah[2][4], al[2][4], bh[2][4], bl[2][4];
            #pragma unroll
            for (int tm = 0; tm < 2; tm++) {
                ldsm4(ah[tm], sA  + a_off + tm*1280 + ks*32);
                ldsm4(al[tm], sAl + a_off + tm*1280 + ks*32);
            }
            #pragma unroll
            for (int p = 0; p < 2; p++) {
                ldsm4(bh[p], sBh + b_off + p*1280 + ks*32);
                ldsm4(bl[p], sBl + b_off + p*1280 + ks*32);
            }
            // pass 1: Ah*Bh
            #pragma unroll
            for (int tm = 0; tm < 2; tm++)
                #pragma unroll
                for (int p = 0; p < 2; p++) {
                    mma_bf16(acc[tm][2*p],   ah[tm], &bh[p][0]);
                    mma_bf16(acc[tm][2*p+1], ah[tm], &bh[p][2]);
                }
            // pass 2: Ah*Bl
            #pragma unroll
            for (int tm = 0; tm < 2; tm++)
                #pragma unroll
                for (int p = 0; p < 2; p++) {
                    mma_bf16(acc[tm][2*p],   ah[tm], &bl[p][0]);
                    mma_bf16(acc[tm][2*p+1], ah[tm], &bl[p][2]);
                }
            // pass 3: Al*Bh
            #pragma unroll
            for (int tm = 0; tm < 2; tm++)
                #pragma unroll
                for (int p = 0; p < 2; p++) {
                    mma_bf16(acc[tm][2*p],   al[tm], &bh[p][0]);
                    mma_bf16(acc[tm][2*p+1], al[tm], &bh[p][2]);
                }
        }
        // issue next-stage loads per-warp, immediately after this warp's compute.
        // target buffer = (it+2)%3 == (it-1)%3, whose readers were fenced by the sync above.
        int ldbuf = buf + 2; if (ldbuf >= NSTG) ldbuf -= NSTG;
        if (it + 2 < iters) LOAD_STAGE(it + 2, ldbuf);
        CP_COMMIT();
        buf = (buf + 1 == NSTG) ? 0 : buf + 1;
    }
    #undef LOAD_STAGE

    int m_base = bm + wm*32 + (lane >> 2);
    int n_base = bn + wn*32 + (lane & 3)*2;
    #pragma unroll
    for (int tm = 0; tm < 2; tm++) {
        #pragma unroll
        for (int tn = 0; tn < 4; tn++) {
            #pragma unroll
            for (int half = 0; half < 2; half++) {
                int m = m_base + tm*16 + half*8;
                int n = n_base + tn*8;
                float v0 = acc[tm][tn][2*half]     + bias[n];
                float v1 = acc[tm][tn][2*half + 1] + bias[n + 1];
                size_t idx = (size_t)m * Ntot + n;
                if (op == 1) {
                    float gv0 = 0.5f * v0 * (1.0f + erff(v0 * 0.70710678118654752f));
                    float gv1 = 0.5f * v1 * (1.0f + erff(v1 * 0.70710678118654752f));
                    bf16 h0 = __float2bfloat16(gv0), h1 = __float2bfloat16(gv1);
                    *(uint32_t*)(Oh + idx) = packbb(h0, h1);
                    *(uint32_t*)(Ol + idx) = packbb(
                        __float2bfloat16(gv0 - __bfloat162float(h0)),
                        __float2bfloat16(gv1 - __bfloat162float(h1)));
                } else if (op == 2) {
                    C[idx]     += v0;
                    C[idx + 1] += v1;
                } else if (op == 3) {
                    bf16 h0 = __float2bfloat16(v0), h1 = __float2bfloat16(v1);
                    *(uint32_t*)(Oh + idx) = packbb(h0, h1);
                    *(uint32_t*)(Ol + idx) = packbb(
                        __float2bfloat16(v0 - __bfloat162float(h0)),
                        __float2bfloat16(v1 - __bfloat162float(h1)));
                } else {
                    C[idx]     = v0;
                    C[idx + 1] = v1;
                }
            }
        }
    }
}

// ---------------- tensor-core fused attention ----------------
#define SSTR 520
#define OFF_Q  (64*SSTR*4)
#define OFF_QL (OFF_Q + 9216)
#define OFF_K  (OFF_QL + 9216)
#define OFF_KL (OFF_K + 18432)
#define ATTN_SMEM (OFF_KL + 18432)

__global__ __launch_bounds__(256) void attn_tc(
    const bf16* __restrict__ QKVh, const bf16* __restrict__ QKVl,
    const int* __restrict__ mask, float* __restrict__ attn_out,
    bf16* __restrict__ aoh, bf16* __restrict__ aol)
{
    extern __shared__ char sm[];
    float* S = (float*)sm;
    uint32_t su = smem_to_u32(sm);
    int tid = threadIdx.x, lane = tid & 31, wid = tid >> 5;
    int q0 = blockIdx.x * 64;
    int h = blockIdx.y, b = blockIdx.z;

    {
        int r = tid >> 2, c = tid & 3;
        size_t g = ((size_t)(b*LL + q0 + r)) * NQKV + h*DH;
        const uint4* gh = (const uint4*)(QKVh + g);
        const uint4* gl = (const uint4*)(QKVl + g);
        *(uint4*)(sm + OFF_Q  + r*144 + c*16)     = gh[c];
        *(uint4*)(sm + OFF_Q  + r*144 + (c+4)*16) = gh[c+4];
        *(uint4*)(sm + OFF_QL + r*144 + c*16)     = gl[c];
        *(uint4*)(sm + OFF_QL + r*144 + (c+4)*16) = gl[c+4];
    }

    int wm = wid & 1, wn = wid >> 1;

    for (int kc = 0; kc < 4; kc++) {
        {
            int r = tid >> 1, c0 = (tid & 1) * 4;
            size_t g = ((size_t)(b*LL + kc*128 + r)) * NQKV + 768 + h*DH;
            const uint4* gh = (const uint4*)(QKVh + g);
            const uint4* gl = (const uint4*)(QKVl + g);
            #pragma unroll
            for (int c = 0; c < 4; c++) {
                *(uint4*)(sm + OFF_K  + r*144 + (c0+c)*16) = gh[c0+c];
                *(uint4*)(sm + OFF_KL + r*144 + (c0+c)*16) = gl[c0+c];
            }
        }
        __syncthreads();
        float acc[2][4][4];
        #pragma unroll
        for (int i = 0; i < 2; i++)
            #pragma unroll
            for (int j = 0; j < 4; j++)
                #pragma unroll
                for (int q = 0; q < 4; q++) acc[i][j][q] = 0.0f;
        uint32_t aoff = (uint32_t)((wm*32 + (lane & 15)) * 144 + 16 * (lane >> 4));
        uint32_t boff = (uint32_t)((wn*32 + 8*((lane >> 4) & 1) + (lane & 7)) * 144
                                   + 16 * ((lane >> 3) & 1));
        #pragma unroll
        for (int ki = 0; ki < 4; ki++) {
            uint32_t ah[2][4], al[2][4], bh[2][4], bl[2][4];
            #pragma unroll
            for (int tm = 0; tm < 2; tm++) {
                ldsm4(ah[tm], su + OFF_Q  + aoff + tm*2304 + ki*32);
                ldsm4(al[tm], su + OFF_QL + aoff + tm*2304 + ki*32);
            }
            #pragma unroll
            for (int p = 0; p < 2; p++) {
                ldsm4(bh[p], su + OFF_K  + boff + p*2304 + ki*32);
                ldsm4(bl[p], su + OFF_KL + boff + p*2304 + ki*32);
            }
            #pragma unroll
            for (int tm = 0; tm < 2; tm++)
                #pragma unroll
                for (int p = 0; p < 2; p++) {
                    mma_bf16(acc[tm][2*p],   ah[tm], &bh[p][0]);
                    mma_bf16(acc[tm][2*p+1], ah[tm], &bh[p][2]);
                }
            #pragma unroll
            for (int tm = 0; tm < 2; tm++)
                #pragma unroll
                for (int p = 0; p < 2; p++) {
                    mma_bf16(acc[tm][2*p],   ah[tm], &bl[p][0]);
                    mma_bf16(acc[tm][2*p+1], ah[tm], &bl[p][2]);
                }
            #pragma unroll
            for (int tm = 0; tm < 2; tm++)
                #pragma unroll
                for (int p = 0; p < 2; p++) {
                    mma_bf16(acc[tm][2*p],   al[tm], &bh[p][0]);
                    mma_bf16(acc[tm][2*p+1], al[tm], &bh[p][2]);
                }
        }
        #pragma unroll
        for (int tm = 0; tm < 2; tm++) {
            #pragma unroll
            for (int tn = 0; tn < 4; tn++) {
                int row = wm*32 + tm*16 + (lane >> 2);
                int col = kc*128 + wn*32 + tn*8 + (lane & 3)*2;
                int m0 = mask[b*LL + col], m1 = mask[b*LL + col + 1];
                #pragma unroll
                for (int half = 0; half < 2; half++) {
                    int rr = row + half*8;
                    float v0 = acc[tm][tn][2*half]   * 0.125f - 0.01f * (float)((q0 + rr) - col);
                    float v1 = acc[tm][tn][2*half+1] * 0.125f - 0.01f * (float)((q0 + rr) - (col+1));
                    if (m0 == 0) v0 = -INFINITY;
                    if (m1 == 0) v1 = -INFINITY;
                    S[rr*SSTR + col]     = v0;
                    S[rr*SSTR + col + 1] = v1;
                }
            }
        }
        __syncthreads();
    }

    {
        size_t gbase0 = ((size_t)(b*HH + h) * LL + q0) * LL;
        #pragma unroll
        for (int j = 0; j < 8; j++) {
            int r = wid*8 + j;
            float4 e[4];
            #pragma unroll
            for (int i = 0; i < 4; i++) e[i] = *(float4*)&S[r*SSTR + i*128 + lane*4];
            float mx = -1e30f;
            #pragma unroll
            for (int i = 0; i < 4; i++)
                mx = fmaxf(mx, fmaxf(fmaxf(e[i].x, e[i].y), fmaxf(e[i].z, e[i].w)));
            #pragma unroll
            for (int o = 16; o > 0; o >>= 1) mx = fmaxf(mx, __shfl_xor_sync(0xFFFFFFFFu, mx, o));
            float sum = 0.0f;
            #pragma unroll
            for (int i = 0; i < 4; i++) {
                e[i].x = __expf(e[i].x - mx); e[i].y = __expf(e[i].y - mx);
                e[i].z = __expf(e[i].z - mx); e[i].w = __expf(e[i].w - mx);
                sum += e[i].x + e[i].y + e[i].z + e[i].w;
            }
            #pragma unroll
            for (int o = 16; o > 0; o >>= 1) sum += __shfl_xor_sync(0xFFFFFFFFu, sum, o);
            float inv = 1.0f / sum;
            float* gp = attn_out + gbase0 + (size_t)r * LL;
            #pragma unroll
            for (int i = 0; i < 4; i++) {
                e[i].x *= inv; e[i].y *= inv; e[i].z *= inv; e[i].w *= inv;
                *(float4*)&S[r*SSTR + i*128 + lane*4] = e[i];
                *(float4*)(gp + i*128 + lane*4) = e[i];
            }
        }
    }
    __syncthreads();

    float oa[2][2][4];
    #pragma unroll
    for (int i = 0; i < 2; i++)
        #pragma unroll
        for (int j = 0; j < 2; j++)
            #pragma unroll
            for (int q = 0; q < 4; q++) oa[i][j][q] = 0.0f;

    for (int kc = 0; kc < 8; kc++) {
        {
            int r = tid >> 2, c0 = (tid & 3) * 16;
            #pragma unroll
            for (int jj = 0; jj < 2; jj++) {
                const float* sp = &S[r*SSTR + kc*64 + c0 + jj*8];
                float v[8];
                *(float4*)&v[0] = *(const float4*)sp;
                *(float4*)&v[4] = *(const float4*)(sp + 4);
                uint32_t hw[4], lw[4];
                #pragma unroll
                for (int q = 0; q < 4; q++) {
                    bf16 ha = __float2bfloat16(v[2*q]), hb = __float2bfloat16(v[2*q+1]);
                    hw[q] = packbb(ha, hb);
                    lw[q] = packbb(__float2bfloat16(v[2*q]   - __bfloat162float(ha)),
                                   __float2bfloat16(v[2*q+1] - __bfloat162float(hb)));
                }
                *(uint4*)(sm + OFF_Q  + r*144 + (c0 + jj*8)*2) = *(uint4*)hw;
                *(uint4*)(sm + OFF_QL + r*144 + (c0 + jj*8)*2) = *(uint4*)lw;
            }
        }
        {
            int r = tid >> 2, c = tid & 3;
            size_t g = ((size_t)(b*LL + kc*64 + r)) * NQKV + 1536 + h*DH;
            const uint4* gh = (const uint4*)(QKVh + g);
            const uint4* gl = (const uint4*)(QKVl + g);
            *(uint4*)(sm + OFF_K  + r*144 + c*16)     = gh[c];
            *(uint4*)(sm + OFF_K  + r*144 + (c+4)*16) = gh[c+4];
            *(uint4*)(sm + OFF_KL + r*144 + c*16)     = gl[c];
            *(uint4*)(sm + OFF_KL + r*144 + (c+4)*16) = gl[c+4];
        }
        __syncthreads();
        uint32_t poff = (uint32_t)((wm*32 + (lane & 15)) * 144 + 16 * (lane >> 4));
        uint32_t voff = (uint32_t)((lane & 15) * 144 + wn*32 + 16 * (lane >> 4));
        #pragma unroll
        for (int ki = 0; ki < 4; ki++) {
            uint32_t ph[2][4], pl[2][4], vh[4], vl[4];
            #pragma unroll
            for (int tm = 0; tm < 2; tm++) {
                ldsm4(ph[tm], su + OFF_Q  + poff + tm*2304 + ki*32);
                ldsm4(pl[tm], su + OFF_QL + poff + tm*2304 + ki*32);
            }
            ldsm4t(vh, su + OFF_K  + voff + ki*2304);
            ldsm4t(vl, su + OFF_KL + voff + ki*2304);
            #pragma unroll
            for (int tm = 0; tm < 2; tm++)
                #pragma unroll
                for (int tn = 0; tn < 2; tn++)
                    mma_bf16(oa[tm][tn], ph[tm], &vh[2*tn]);
            #pragma unroll
            for (int tm = 0; tm < 2; tm++)
                #pragma unroll
                for (int tn = 0; tn < 2; tn++)
                    mma_bf16(oa[tm][tn], ph[tm], &vl[2*tn]);
            #pragma unroll
            for (int tm = 0; tm < 2; tm++)
                #pragma unroll
                for (int tn = 0; tn < 2; tn++)
                    mma_bf16(oa[tm][tn], pl[tm], &vh[2*tn]);
        }
        __syncthreads();
    }

    #pragma unroll
    for (int tm = 0; tm < 2; tm++) {
        #pragma unroll
        for (int tn = 0; tn < 2; tn++) {
            #pragma unroll
            for (int half = 0; half < 2; half++) {
                int row = wm*32 + tm*16 + (lane >> 2) + half*8;
                int col = wn*16 + tn*8 + (lane & 3)*2;
                float v0 = oa[tm][tn][2*half], v1 = oa[tm][tn][2*half+1];
                size_t g = ((size_t)(b*LL + q0 + row)) * DD + h*DH + col;
                bf16 h0 = __float2bfloat16(v0), h1 = __float2bfloat16(v1);
                *(uint32_t*)(aoh + g) = packbb(h0, h1);
                *(uint32_t*)(aol + g) = packbb(
                    __float2bfloat16(v0 - __bfloat162float(h0)),
                    __float2bfloat16(v1 - __bfloat162float(h1)));
            }
        }
    }
}

// ---------------- classifier head ----------------
__global__ void logits_kernel(const float* __restrict__ h, const float* __restrict__ Wc,
                              const float* __restrict__ bc, float* __restrict__ out) {
    __shared__ float red[256];
    int b = blockIdx.x;
    int t = threadIdx.x;
    float s = 0.0f;
    for (int d = t; d < DD; d += 256) s += h[(size_t)b * LL * DD + d] * Wc[d * NC];
    red[t] = s; __syncthreads();
    for (int o = 128; o > 0; o >>= 1) { if (t < o) red[t] += red[t + o]; __syncthreads(); }
    if (t == 0) out[b * NC] = red[0] + bc[0];
}

// ---------------- launcher ----------------
extern "C" void kernel_launch(void* const* d_in, const int* in_sizes, int n_in,
                              void* d_out, int out_size) {
    const int*   x    = (const int*)  d_in[0];
    const int*   mask = (const int*)  d_in[1];
    const float* emb  = (const float*)d_in[2];
    const float* Wq   = (const float*)d_in[3];
    const float* bq   = (const float*)d_in[4];
    const float* Wk   = (const float*)d_in[5];
    const float* bk   = (const float*)d_in[6];
    const float* Wv   = (const float*)d_in[7];
    const float* bv   = (const float*)d_in[8];
    const float* Wo   = (const float*)d_in[9];
    const float* bo   = (const float*)d_in[10];
    const float* W1   = (const float*)d_in[11];
    const float* b1   = (const float*)d_in[12];
    const float* W2   = (const float*)d_in[13];
    const float* b2   = (const float*)d_in[14];
    const float* g1   = (const float*)d_in[15];
    const float* be1  = (const float*)d_in[16];
    const float* g2   = (const float*)d_in[17];
    const float* be2  = (const float*)d_in[18];
    const float* Wc   = (const float*)d_in[19];
    const float* bc   = (const float*)d_in[20];

    float* out = (float*)d_out;
    float* logits = out;
    float* attn_base = out + (size_t)BB * NC;

    static bool attr_set = false;
    if (!attr_set) {
        cudaFuncSetAttribute(gemm_mma, cudaFuncAttributeMaxDynamicSharedMemorySize, GEMM_SMEM);
        cudaFuncSetAttribute(attn_tc, cudaFuncAttributeMaxDynamicSharedMemorySize, ATTN_SMEM);
        attr_set = true;
    }

    float *p_h, *p_bqkv;
    bf16 *p_xnh, *p_xnl, *p_qkvh, *p_qkvl, *p_aoh, *p_aol, *p_ffh, *p_ffl;
    bf16 *p_wqkvh, *p_wqkvl, *p_woh, *p_wol, *p_w1h, *p_w1l, *p_w2h, *p_w2l;
    cudaGetSymbolAddress((void**)&p_h, g_h);
    cudaGetSymbolAddress((void**)&p_bqkv, g_bqkv);
    cudaGetSymbolAddress((void**)&p_xnh, g_xnh); cudaGetSymbolAddress((void**)&p_xnl, g_xnl);
    cudaGetSymbolAddress((void**)&p_qkvh, g_qkvh); cudaGetSymbolAddress((void**)&p_qkvl, g_qkvl);
    cudaGetSymbolAddress((void**)&p_aoh, g_aoh); cudaGetSymbolAddress((void**)&p_aol, g_aol);
    cudaGetSymbolAddress((void**)&p_ffh, g_ffh); cudaGetSymbolAddress((void**)&p_ffl, g_ffl);
    cudaGetSymbolAddress((void**)&p_wqkvh, g_wqkvh); cudaGetSymbolAddress((void**)&p_wqkvl, g_wqkvl);
    cudaGetSymbolAddress((void**)&p_woh, g_woh); cudaGetSymbolAddress((void**)&p_wol, g_wol);
    cudaGetSymbolAddress((void**)&p_w1h, g_w1h); cudaGetSymbolAddress((void**)&p_w1l, g_w1l);
    cudaGetSymbolAddress((void**)&p_w2h, g_w2h); cudaGetSymbolAddress((void**)&p_w2l, g_w2l);

    dim3 tb(32, 8);
    size_t olsQKV = (size_t)NQKV * DD;

    // Launch order chosen so the QKV gemm_mma is launch #6 (ncu -s 5 -c 1 captures it):
    // 1: tsplit_qkv  2: tsplit(Wo)  3: bias_concat  4: embed  5: ln  6: gemm_mma(QKV)
    tsplit_qkv<<<dim3(DD/32, DD/32, NL*3), tb>>>(Wq, Wk, Wv, p_wqkvh, p_wqkvl);
    tsplit_kernel<<<dim3(DD/32, DD/32, NL), tb>>>(Wo, p_woh, p_wol, DD, DD, 0, (size_t)DD*DD);
    bias_concat<<<dim3(NQKV/256, NL), 256>>>(bq, bk, bv, p_bqkv);
    embed_kernel<<<MM, 256>>>(x, emb, p_h);

    dim3 gD(DD/64, MM/128);
    dim3 gQKV(NQKV/64, MM/128);
    dim3 gF(FF/64, MM/128);
    dim3 gAttn(LL/64, HH, BB);

    for (int l = 0; l < NL; l++) {
        size_t wD = (size_t)l * DD * DD;
        size_t wF = (size_t)l * DD * FF;
        size_t wQ = (size_t)l * olsQKV;
        ln_kernel<<<MM, 256>>>(p_h, g1 + l*DD, be1 + l*DD, p_xnh, p_xnl);
        gemm_mma<<<gQKV, 256, GEMM_SMEM>>>(p_xnh, p_xnl, p_wqkvh + wQ, p_wqkvl + wQ,
                                           p_bqkv + l*NQKV, nullptr, p_qkvh, p_qkvl, NQKV, DD, 3);
        if (l == 0) {
            // W1/W2 splits needed from here on; launched after the profiled QKV GEMM
            tsplit_kernel<<<dim3(FF/32, DD/32, NL), tb>>>(W1, p_w1h, p_w1l, DD, FF, 0, (size_t)DD*FF);
            tsplit_kernel<<<dim3(DD/32, FF/32, NL), tb>>>(W2, p_w2h, p_w2l, FF, DD, 0, (size_t)FF*DD);
        }
        attn_tc<<<gAttn, 256, ATTN_SMEM>>>(p_qkvh, p_qkvl, mask,
                                           attn_base + (size_t)l * BB * HH * LL * LL, p_aoh, p_aol);
        gemm_mma<<<gD, 256, GEMM_SMEM>>>(p_aoh, p_aol, p_woh + wD, p_wol + wD, bo + l*DD,
                                         p_h, nullptr, nullptr, DD, DD, 2);
        ln_kernel<<<MM, 256>>>(p_h, g2 + l*DD, be2 + l*DD, p_xnh, p_xnl);
        gemm_mma<<<gF, 256, GEMM_SMEM>>>(p_xnh, p_xnl, p_w1h + wF, p_w1l + wF, b1 + l*FF,
                                         nullptr, p_ffh, p_ffl, FF, DD, 1);
        gemm_mma<<<gD, 256, GEMM_SMEM>>>(p_ffh, p_ffl, p_w2h + wF, p_w2l + wF, b2 + l*DD,
                                         p_h, nullptr, nullptr, DD, FF, 2);
    }

    logits_kernel<<<BB, 256>>>(p_h, Wc, bc, logits);
}